// round 7
// baseline (speedup 1.0000x reference)
#include <cuda_runtime.h>
#include <cuda_bf16.h>
#include <cstdint>

// Problem dims
#define Bdim 4
#define Mdim 256
#define Ndim 128
#define Ddim 512
#define Cdim 1024
#define ROWS (Bdim*Mdim*Ndim)   // 131072

// -------- scratch (device globals) --------
__device__ float g_he[Bdim*Mdim*Ddim];          // 2 MB
__device__ float g_hd[Bdim*Ndim*Ddim];          // 1 MB
__device__ __nv_bfloat16 g_w2b[Cdim*Ddim];      // 1 MB   w2 -> bf16
__device__ __nv_bfloat16 g_H[(size_t)ROWS*Ddim];// 134 MB H = tanh(...) bf16
__device__ float g_part[(size_t)ROWS*32];       // 16 MB (max,sum) x16 per row
__device__ float g_lse[ROWS];                   // 0.5 MB

// -------- helpers --------
__device__ __forceinline__ float tanh_fast(float x){
    float r; asm("tanh.approx.f32 %0, %1;" : "=f"(r) : "f"(x)); return r;
}
__device__ __forceinline__ unsigned pk(float lo, float hi){
    unsigned r;
    asm("cvt.rn.bf16x2.f32 %0, %2, %1;" : "=r"(r) : "f"(lo), "f"(hi));
    return r;
}
__device__ __forceinline__ void mma_bf16(float* d, const unsigned* a, const unsigned* b){
    asm volatile(
        "mma.sync.aligned.m16n8k16.row.col.f32.bf16.bf16.f32 "
        "{%0,%1,%2,%3}, {%4,%5,%6,%7}, {%8,%9}, {%0,%1,%2,%3};\n"
        : "+f"(d[0]), "+f"(d[1]), "+f"(d[2]), "+f"(d[3])
        : "r"(a[0]), "r"(a[1]), "r"(a[2]), "r"(a[3]), "r"(b[0]), "r"(b[1]));
}
__device__ __forceinline__ unsigned smem_u32(const void* p){
    unsigned a;
    asm("{ .reg .u64 t; cvta.to.shared.u64 t, %1; cvt.u32.u64 %0, t; }" : "=r"(a) : "l"(p));
    return a;
}
__device__ __forceinline__ void cpa16(unsigned saddr, const void* g){
    asm volatile("cp.async.cg.shared.global [%0], [%1], 16;" :: "r"(saddr), "l"(g));
}
#define CPA_COMMIT() asm volatile("cp.async.commit_group;" ::: "memory")
#define CPA_WAIT1()  asm volatile("cp.async.wait_group 1;" ::: "memory")

// ================= K0: w2 -> bf16 =================
__global__ __launch_bounds__(256) void cvtw2b_k(const float* __restrict__ w2){
    const int i = blockIdx.x*256 + threadIdx.x;
    float4 v0 = ((const float4*)w2)[2*i];
    float4 v1 = ((const float4*)w2)[2*i + 1];
    uint4 o;
    o.x = pk(v0.x, v0.y); o.y = pk(v0.z, v0.w);
    o.z = pk(v1.x, v1.y); o.w = pk(v1.z, v1.w);
    ((uint4*)g_w2b)[i] = o;
}

// ================= K1: fc1 small GEMMs (fp32, exact) =================
__global__ __launch_bounds__(256) void fc1_k(const float* __restrict__ X,
                                             const float* __restrict__ W,
                                             int woff, int which){
    __shared__ float sX[16][64];
    __shared__ float sW[16][64];
    float* __restrict__ Y = which ? g_hd : g_he;
    const int t  = threadIdx.x;
    const int tx = t & 15, ty = t >> 4;
    const int rb = blockIdx.y << 6, eb = blockIdx.x << 6;
    const int r  = t >> 2, kq = (t & 3) << 2;

    float acc[4][4];
#pragma unroll
    for (int i = 0; i < 4; i++)
#pragma unroll
        for (int j = 0; j < 4; j++) acc[i][j] = 0.f;

    for (int k0 = 0; k0 < Ddim; k0 += 16){
        float4 xv = *(const float4*)(X + (rb + r)*Ddim + k0 + kq);
        float4 wv = *(const float4*)(W + (eb + r)*(2*Ddim) + woff + k0 + kq);
        __syncthreads();
        sX[kq+0][r] = xv.x; sX[kq+1][r] = xv.y; sX[kq+2][r] = xv.z; sX[kq+3][r] = xv.w;
        sW[kq+0][r] = wv.x; sW[kq+1][r] = wv.y; sW[kq+2][r] = wv.z; sW[kq+3][r] = wv.w;
        __syncthreads();
#pragma unroll
        for (int k = 0; k < 16; k++){
            float4 a  = *(const float4*)&sX[k][ty << 2];
            float4 bv = *(const float4*)&sW[k][tx << 2];
            float av[4] = {a.x, a.y, a.z, a.w};
            float bb[4] = {bv.x, bv.y, bv.z, bv.w};
#pragma unroll
            for (int i = 0; i < 4; i++)
#pragma unroll
                for (int j = 0; j < 4; j++) acc[i][j] = fmaf(av[i], bb[j], acc[i][j]);
        }
    }
#pragma unroll
    for (int i = 0; i < 4; i++)
#pragma unroll
        for (int j = 0; j < 4; j++)
            Y[(rb + (ty<<2) + i)*Ddim + eb + (tx<<2) + j] = acc[i][j];
}

// ================= K2: H = bf16(tanh(he + hd + b1)), computed ONCE ============
__global__ __launch_bounds__(256) void tanh_k(const float* __restrict__ b1){
    __shared__ float sHE[512];
    const int bm = blockIdx.x;          // 0..1023
    const int b  = bm >> 8;
    const int t  = threadIdx.x;
    if (t < 128){
        float4 h  = ((const float4*)(g_he + bm*Ddim))[t];
        float4 bb = ((const float4*)b1)[t];
        float4 v; v.x=h.x+bb.x; v.y=h.y+bb.y; v.z=h.z+bb.z; v.w=h.w+bb.w;
        ((float4*)sHE)[t] = v;
    }
    __syncthreads();
    const float* hdB = g_hd + ((size_t)b << 16);
    __nv_bfloat16* Hb = g_H + ((size_t)bm << 16);
#pragma unroll 4
    for (int i = t; i < 128*64; i += 256){
        const int n = i >> 6;
        const int k = (i & 63) << 3;
        float4 d0 = *(const float4*)(hdB + n*Ddim + k);
        float4 d1 = *(const float4*)(hdB + n*Ddim + k + 4);
        float4 h0 = *(const float4*)(sHE + k);
        float4 h1 = *(const float4*)(sHE + k + 4);
        uint4 o;
        o.x = pk(tanh_fast(h0.x + d0.x), tanh_fast(h0.y + d0.y));
        o.y = pk(tanh_fast(h0.z + d0.z), tanh_fast(h0.w + d0.w));
        o.z = pk(tanh_fast(h1.x + d1.x), tanh_fast(h1.y + d1.y));
        o.w = pk(tanh_fast(h1.z + d1.z), tanh_fast(h1.w + d1.w));
        *(uint4*)(Hb + n*Ddim + k) = o;
    }
}

// ================= K3: bf16 GEMM C = H x w2^T, cp.async pipeline ===============
// CTA 256 rows x 128 cols, 256 threads, 8 warps 4(m)x2(n), warp tile 64x64.
// 3 smem stages x (A 256x80B + B 128x80B); one barrier per k32 chunk.
#define PITCH 80
#define BOFF  20480
#define STAGE 30720
#define NST   3

__global__ __launch_bounds__(256,1) void gemm_k(const float* __restrict__ b2,
                                                float* __restrict__ out){
    extern __shared__ __align__(128) char smem[];
    const unsigned sb = smem_u32(smem);
    const int t   = threadIdx.x;
    const int w   = t >> 5, l = t & 31;
    const int wm  = w >> 1, wn = w & 1;
    const int lq  = l >> 2, lr = l & 3;
    const int bid = blockIdx.x;
    const int rt  = bid >> 3, ci = bid & 7;
    const int g0  = rt << 8;
    const int cb  = ci << 7;

    // copy source/dest addresses
    const char* aG = (const char*)(g_H + (size_t)(g0 + t)*Ddim);
    const char* bG = (const char*)(g_w2b + (size_t)(cb + (t & 127))*Ddim) + ((t >> 7) << 5);
    const unsigned sA  = sb + t*PITCH;
    const unsigned sBb = sb + BOFF + (t & 127)*PITCH + ((t >> 7) << 5);

    float acc[4][8][4];
#pragma unroll
    for (int mt = 0; mt < 4; mt++)
#pragma unroll
        for (int nt = 0; nt < 8; nt++)
#pragma unroll
            for (int i = 0; i < 4; i++) acc[mt][nt][i] = 0.f;

    // prologue: stage chunks 0 and 1
#pragma unroll
    for (int s = 0; s < 2; s++){
        const char* ag = aG + s*64;
        const char* bg = bG + s*64;
#pragma unroll
        for (int j = 0; j < 4; j++) cpa16(sA + s*STAGE + (j << 4), ag + (j << 4));
        cpa16(sBb + s*STAGE,      bg);
        cpa16(sBb + s*STAGE + 16, bg + 16);
        CPA_COMMIT();
    }

#pragma unroll 1
    for (int kc = 0; kc < 16; kc++){
        CPA_WAIT1();          // chunk kc resident
        __syncthreads();      // also protects stage being overwritten below
        // issue copy for chunk kc+2 into stage (kc+2)%3
        if (kc < 14){
            const int ws = (kc + 2) % NST;
            const char* ag = aG + (kc + 2)*64;
            const char* bg = bG + (kc + 2)*64;
#pragma unroll
            for (int j = 0; j < 4; j++) cpa16(sA + ws*STAGE + (j << 4), ag + (j << 4));
            cpa16(sBb + ws*STAGE,      bg);
            cpa16(sBb + ws*STAGE + 16, bg + 16);
        }
        CPA_COMMIT();
        // mma over chunk kc (2 k16 steps)
        const char* A  = smem + (kc % NST)*STAGE;
        const char* Bm = A + BOFF;
#pragma unroll
        for (int s = 0; s < 2; s++){
            const int off = (s << 5) + (lr << 2);
            unsigned af[4][4], bf[8][2];
#pragma unroll
            for (int mt = 0; mt < 4; mt++){
                const char* ap = A + ((wm << 6) + (mt << 4) + lq)*PITCH + off;
                af[mt][0] = *(const unsigned*)ap;
                af[mt][1] = *(const unsigned*)(ap + 8*PITCH);
                af[mt][2] = *(const unsigned*)(ap + 16);
                af[mt][3] = *(const unsigned*)(ap + 8*PITCH + 16);
            }
#pragma unroll
            for (int nt = 0; nt < 8; nt++){
                const char* bp = Bm + ((wn << 6) + (nt << 3) + lq)*PITCH + off;
                bf[nt][0] = *(const unsigned*)bp;
                bf[nt][1] = *(const unsigned*)(bp + 16);
            }
#pragma unroll
            for (int mt = 0; mt < 4; mt++)
#pragma unroll
                for (int nt = 0; nt < 8; nt++)
                    mma_bf16(acc[mt][nt], af[mt], bf[nt]);
        }
    }

    // ---- epilogue: +b2, store logits, per-row online (max, sumexp) partials ----
    const int colb = (ci << 7) + (wn << 6);
#pragma unroll
    for (int mt = 0; mt < 4; mt++){
#pragma unroll
        for (int h = 0; h < 2; h++){
            const int r = (wm << 6) + (mt << 4) + lq + (h << 3);
            const int g = g0 + r;
            float v[16];
            float mx = -3.4e38f;
#pragma unroll
            for (int nt = 0; nt < 8; nt++){
                const int c = colb + (nt << 3) + (lr << 1);
                float x0 = acc[mt][nt][h*2 + 0] + __ldg(b2 + c);
                float x1 = acc[mt][nt][h*2 + 1] + __ldg(b2 + c + 1);
                v[2*nt] = x0; v[2*nt + 1] = x1;
                mx = fmaxf(mx, fmaxf(x0, x1));
                float2 st; st.x = x0; st.y = x1;
                *(float2*)(out + (size_t)g*Cdim + c) = st;
            }
            mx = fmaxf(mx, __shfl_xor_sync(0xffffffffu, mx, 1));
            mx = fmaxf(mx, __shfl_xor_sync(0xffffffffu, mx, 2));
            float s = 0.f;
#pragma unroll
            for (int i = 0; i < 16; i++) s += __expf(v[i] - mx);
            s += __shfl_xor_sync(0xffffffffu, s, 1);
            s += __shfl_xor_sync(0xffffffffu, s, 2);
            if (lr == 0){
                float2 p; p.x = mx; p.y = s;
                *(float2*)(g_part + (size_t)g*32 + (((ci << 1) + wn) << 1)) = p;
            }
        }
    }
}

// ================= K4: combine 16 partials/row -> lse =================
__global__ __launch_bounds__(256) void lse_k(){
    const int g = blockIdx.x*256 + threadIdx.x;
    const float* p = g_part + (size_t)g*32;
    float pm[16], ps[16];
    float mx = -3.4e38f;
#pragma unroll
    for (int i = 0; i < 16; i++){ pm[i] = p[2*i]; ps[i] = p[2*i + 1]; mx = fmaxf(mx, pm[i]); }
    float s = 0.f;
#pragma unroll
    for (int i = 0; i < 16; i++) s += ps[i]*__expf(pm[i] - mx);
    g_lse[g] = mx + __logf(s);
}

// ================= K5: out[row, c] -= lse[row] =================
__global__ __launch_bounds__(256) void sub_k(float* __restrict__ out){
    const size_t i = (size_t)blockIdx.x*256 + threadIdx.x;   // float4 index
    const float l = __ldg(g_lse + (i >> 8));
    float4 v = ((const float4*)out)[i];
    v.x -= l; v.y -= l; v.z -= l; v.w -= l;
    ((float4*)out)[i] = v;
}

// ================= launch =================
extern "C" void kernel_launch(void* const* d_in, const int* in_sizes, int n_in,
                              void* d_out, int out_size){
    (void)in_sizes; (void)n_in; (void)out_size;
    const float* enc = (const float*)d_in[0];
    const float* dec = (const float*)d_in[1];
    const float* w1  = (const float*)d_in[2];
    const float* b1  = (const float*)d_in[3];
    const float* w2  = (const float*)d_in[4];
    const float* b2  = (const float*)d_in[5];
    float* out = (float*)d_out;

    cudaFuncSetAttribute(gemm_k, cudaFuncAttributeMaxDynamicSharedMemorySize, NST*STAGE);

    cvtw2b_k<<<(Cdim*Ddim/8)/256, 256>>>(w2);
    fc1_k<<<dim3(8, 16), 256>>>(enc, w1, 0,    0);   // he
    fc1_k<<<dim3(8, 8),  256>>>(dec, w1, Ddim, 1);   // hd
    tanh_k<<<Bdim*Mdim, 256>>>(b1);
    gemm_k<<<4096, 256, NST*STAGE>>>(b2, out);
    lse_k<<<ROWS/256, 256>>>();
    sub_k<<<(ROWS*(Cdim/4))/256, 256>>>(out);
}

// round 8
// speedup vs baseline: 1.2361x; 1.2361x over previous
#include <cuda_runtime.h>
#include <cuda_bf16.h>
#include <cstdint>

// Problem dims
#define Bdim 4
#define Mdim 256
#define Ndim 128
#define Ddim 512
#define Cdim 1024
#define ROWS (Bdim*Mdim*Ndim)   // 131072

// -------- scratch (device globals) --------
__device__ float g_he[Bdim*Mdim*Ddim];          // 2 MB
__device__ float g_hd[Bdim*Ndim*Ddim];          // 1 MB
__device__ __nv_bfloat16 g_w2b[Cdim*Ddim];      // 1 MB   w2 -> bf16
__device__ __nv_bfloat16 g_H[(size_t)ROWS*Ddim];// 134 MB H = tanh(...) bf16
__device__ float g_part[(size_t)ROWS*32];       // 16 MB (max,sum) x16 per row
__device__ float g_lse[ROWS];                   // 0.5 MB

// -------- helpers --------
__device__ __forceinline__ float tanh_fast(float x){
    float r; asm("tanh.approx.f32 %0, %1;" : "=f"(r) : "f"(x)); return r;
}
__device__ __forceinline__ unsigned pk(float lo, float hi){
    unsigned r;
    asm("cvt.rn.bf16x2.f32 %0, %2, %1;" : "=r"(r) : "f"(lo), "f"(hi));
    return r;
}
__device__ __forceinline__ void mma_bf16(float* d, const unsigned* a, const unsigned* b){
    asm volatile(
        "mma.sync.aligned.m16n8k16.row.col.f32.bf16.bf16.f32 "
        "{%0,%1,%2,%3}, {%4,%5,%6,%7}, {%8,%9}, {%0,%1,%2,%3};\n"
        : "+f"(d[0]), "+f"(d[1]), "+f"(d[2]), "+f"(d[3])
        : "r"(a[0]), "r"(a[1]), "r"(a[2]), "r"(a[3]), "r"(b[0]), "r"(b[1]));
}

// ================= K0: w2 -> bf16 =================
__global__ __launch_bounds__(256) void cvtw2b_k(const float* __restrict__ w2){
    const int i = blockIdx.x*256 + threadIdx.x;
    float4 v0 = ((const float4*)w2)[2*i];
    float4 v1 = ((const float4*)w2)[2*i + 1];
    uint4 o;
    o.x = pk(v0.x, v0.y); o.y = pk(v0.z, v0.w);
    o.z = pk(v1.x, v1.y); o.w = pk(v1.z, v1.w);
    ((uint4*)g_w2b)[i] = o;
}

// ================= K1: fc1 small GEMMs (fp32, exact) =================
__global__ __launch_bounds__(256) void fc1_k(const float* __restrict__ X,
                                             const float* __restrict__ W,
                                             int woff, int which){
    __shared__ float sX[16][64];
    __shared__ float sW[16][64];
    float* __restrict__ Y = which ? g_hd : g_he;
    const int t  = threadIdx.x;
    const int tx = t & 15, ty = t >> 4;
    const int rb = blockIdx.y << 6, eb = blockIdx.x << 6;
    const int r  = t >> 2, kq = (t & 3) << 2;

    float acc[4][4];
#pragma unroll
    for (int i = 0; i < 4; i++)
#pragma unroll
        for (int j = 0; j < 4; j++) acc[i][j] = 0.f;

    for (int k0 = 0; k0 < Ddim; k0 += 16){
        float4 xv = *(const float4*)(X + (rb + r)*Ddim + k0 + kq);
        float4 wv = *(const float4*)(W + (eb + r)*(2*Ddim) + woff + k0 + kq);
        __syncthreads();
        sX[kq+0][r] = xv.x; sX[kq+1][r] = xv.y; sX[kq+2][r] = xv.z; sX[kq+3][r] = xv.w;
        sW[kq+0][r] = wv.x; sW[kq+1][r] = wv.y; sW[kq+2][r] = wv.z; sW[kq+3][r] = wv.w;
        __syncthreads();
#pragma unroll
        for (int k = 0; k < 16; k++){
            float4 a  = *(const float4*)&sX[k][ty << 2];
            float4 bv = *(const float4*)&sW[k][tx << 2];
            float av[4] = {a.x, a.y, a.z, a.w};
            float bb[4] = {bv.x, bv.y, bv.z, bv.w};
#pragma unroll
            for (int i = 0; i < 4; i++)
#pragma unroll
                for (int j = 0; j < 4; j++) acc[i][j] = fmaf(av[i], bb[j], acc[i][j]);
        }
    }
#pragma unroll
    for (int i = 0; i < 4; i++)
#pragma unroll
        for (int j = 0; j < 4; j++)
            Y[(rb + (ty<<2) + i)*Ddim + eb + (tx<<2) + j] = acc[i][j];
}

// ================= K2: H = bf16(tanh(he + hd + b1)), computed ONCE ============
__global__ __launch_bounds__(256) void tanh_k(const float* __restrict__ b1){
    __shared__ float sHE[512];
    const int bm = blockIdx.x;          // 0..1023
    const int b  = bm >> 8;
    const int t  = threadIdx.x;
    if (t < 128){
        float4 h  = ((const float4*)(g_he + bm*Ddim))[t];
        float4 bb = ((const float4*)b1)[t];
        float4 v; v.x=h.x+bb.x; v.y=h.y+bb.y; v.z=h.z+bb.z; v.w=h.w+bb.w;
        ((float4*)sHE)[t] = v;
    }
    __syncthreads();
    const float* hdB = g_hd + ((size_t)b << 16);
    __nv_bfloat16* Hb = g_H + ((size_t)bm << 16);
#pragma unroll 4
    for (int i = t; i < 128*64; i += 256){
        const int n = i >> 6;
        const int k = (i & 63) << 3;
        float4 d0 = *(const float4*)(hdB + n*Ddim + k);
        float4 d1 = *(const float4*)(hdB + n*Ddim + k + 4);
        float4 h0 = *(const float4*)(sHE + k);
        float4 h1 = *(const float4*)(sHE + k + 4);
        uint4 o;
        o.x = pk(tanh_fast(h0.x + d0.x), tanh_fast(h0.y + d0.y));
        o.y = pk(tanh_fast(h0.z + d0.z), tanh_fast(h0.w + d0.w));
        o.z = pk(tanh_fast(h1.x + d1.x), tanh_fast(h1.y + d1.y));
        o.w = pk(tanh_fast(h1.z + d1.z), tanh_fast(h1.w + d1.w));
        *(uint4*)(Hb + n*Ddim + k) = o;
    }
}

// ================= K3: bf16 GEMM C = H x w2^T (R5 structure, copy producer) ====
// CTA: 256 rows x 128 cols, K=512 in 16 chunks of 32.
// 8 warps as 4(m) x 2(n), warp tile 64x64, mma m16n8k16 bf16.
// smem: sA 2 bufs x 256 rows x 80B, sB 2 bufs x 128 rows x 80B  (= 61440 B)
#define SA_OFF  0
#define SB_OFF  40960
#define A_BUF   20480
#define B_BUF   10240
#define PITCH   80

__global__ __launch_bounds__(256,1) void joint_k(const float* __restrict__ b2,
                                                 float* __restrict__ out){
    extern __shared__ __align__(128) char smemc[];

    const int bid = blockIdx.x;
    const int bm2 = bid >> 3;       // 0..511  (256-row block)
    const int ci  = bid & 7;        // 0..7    (128-col block)
    const int t   = threadIdx.x;
    const int w   = t >> 5, l = t & 31;
    const int wm  = w >> 1, wn = w & 1;
    const int lq  = l >> 2, lr = l & 3;
    const int g0  = bm2 << 8;

    const int pr  = t >> 2;         // 0..63
    const int sc  = (t & 3) << 4;   // 16B slot within row (bytes)

    // global sources: A rows pr + 64k (k=0..3) of this 256-row tile; B rows pr, pr+64
    const char* aGp = (const char*)(g_H + (size_t)(g0 + pr)*Ddim) + sc;
    const char* bGp = (const char*)(g_w2b + (size_t)((ci << 7) + pr)*Ddim) + sc;

    uint4 av[4], bv[2];
    float acc[4][8][4];
#pragma unroll
    for (int mt = 0; mt < 4; mt++)
#pragma unroll
        for (int nt = 0; nt < 8; nt++)
#pragma unroll
            for (int i = 0; i < 4; i++) acc[mt][nt][i] = 0.f;

    // ---- prefetch chunk 0 ----
#pragma unroll
    for (int k = 0; k < 4; k++) av[k] = *(const uint4*)(aGp + (size_t)(k << 6)*Ddim*2);
    bv[0] = *(const uint4*)bGp;
    bv[1] = *(const uint4*)(bGp + (size_t)64*Ddim*2);

    // ---- store chunk 0 into buf 0 ----
#pragma unroll
    for (int k = 0; k < 4; k++)
        *(uint4*)(smemc + SA_OFF + (pr + (k << 6))*PITCH + sc) = av[k];
    *(uint4*)(smemc + SB_OFF + pr*PITCH + sc)        = bv[0];
    *(uint4*)(smemc + SB_OFF + (pr + 64)*PITCH + sc) = bv[1];
    __syncthreads();

    int buf = 0;
#pragma unroll 1
    for (int kc = 0; kc < 16; kc++){
        // prefetch next chunk from global
        if (kc < 15){
            const int ko = (kc + 1) << 6;   // 64 bytes per 32-k chunk
#pragma unroll
            for (int k = 0; k < 4; k++)
                av[k] = *(const uint4*)(aGp + (size_t)(k << 6)*Ddim*2 + ko);
            bv[0] = *(const uint4*)(bGp + ko);
            bv[1] = *(const uint4*)(bGp + (size_t)64*Ddim*2 + ko);
        }
        // mma over current chunk (2 k16 steps)
        {
            const char* A  = smemc + SA_OFF + buf*A_BUF;
            const char* Bm = smemc + SB_OFF + buf*B_BUF;
#pragma unroll
            for (int s = 0; s < 2; s++){
                const int off = (s << 5) + (lr << 2);
                unsigned af[4][4], bf[8][2];
#pragma unroll
                for (int mt = 0; mt < 4; mt++){
                    const char* ap = A + ((wm << 6) + (mt << 4) + lq)*PITCH + off;
                    af[mt][0] = *(const unsigned*)ap;
                    af[mt][1] = *(const unsigned*)(ap + 8*PITCH);
                    af[mt][2] = *(const unsigned*)(ap + 16);
                    af[mt][3] = *(const unsigned*)(ap + 8*PITCH + 16);
                }
#pragma unroll
                for (int nt = 0; nt < 8; nt++){
                    const char* bp = Bm + ((wn << 6) + (nt << 3) + lq)*PITCH + off;
                    bf[nt][0] = *(const unsigned*)bp;
                    bf[nt][1] = *(const unsigned*)(bp + 16);
                }
#pragma unroll
                for (int mt = 0; mt < 4; mt++)
#pragma unroll
                    for (int nt = 0; nt < 8; nt++)
                        mma_bf16(acc[mt][nt], af[mt], bf[nt]);
            }
        }
        // store next chunk into other buffer
        if (kc < 15){
            char* dA = smemc + SA_OFF + (buf ^ 1)*A_BUF;
            char* dB = smemc + SB_OFF + (buf ^ 1)*B_BUF;
#pragma unroll
            for (int k = 0; k < 4; k++)
                *(uint4*)(dA + (pr + (k << 6))*PITCH + sc) = av[k];
            *(uint4*)(dB + pr*PITCH + sc)        = bv[0];
            *(uint4*)(dB + (pr + 64)*PITCH + sc) = bv[1];
        }
        __syncthreads();
        buf ^= 1;
    }

    // ---- epilogue: +b2, store logits, per-row online (max, sumexp) partials ----
    const int colb = (ci << 7) + (wn << 6);
#pragma unroll
    for (int mt = 0; mt < 4; mt++){
#pragma unroll
        for (int h = 0; h < 2; h++){
            const int r = (wm << 6) + (mt << 4) + lq + (h << 3);
            const int g = g0 + r;
            float v[16];
            float mx = -3.4e38f;
#pragma unroll
            for (int nt = 0; nt < 8; nt++){
                const int c = colb + (nt << 3) + (lr << 1);
                float x0 = acc[mt][nt][h*2 + 0] + __ldg(b2 + c);
                float x1 = acc[mt][nt][h*2 + 1] + __ldg(b2 + c + 1);
                v[2*nt] = x0; v[2*nt + 1] = x1;
                mx = fmaxf(mx, fmaxf(x0, x1));
                float2 st; st.x = x0; st.y = x1;
                *(float2*)(out + (size_t)g*Cdim + c) = st;
            }
            mx = fmaxf(mx, __shfl_xor_sync(0xffffffffu, mx, 1));
            mx = fmaxf(mx, __shfl_xor_sync(0xffffffffu, mx, 2));
            float s = 0.f;
#pragma unroll
            for (int i = 0; i < 16; i++) s += __expf(v[i] - mx);
            s += __shfl_xor_sync(0xffffffffu, s, 1);
            s += __shfl_xor_sync(0xffffffffu, s, 2);
            if (lr == 0){
                float2 p; p.x = mx; p.y = s;
                *(float2*)(g_part + (size_t)g*32 + (((ci << 1) + wn) << 1)) = p;
            }
        }
    }
}

// ================= K4: combine 16 partials/row -> lse =================
__global__ __launch_bounds__(256) void lse_k(){
    const int g = blockIdx.x*256 + threadIdx.x;
    const float4* p4 = (const float4*)(g_part + (size_t)g*32);
    float pm[16], ps[16];
    float mx = -3.4e38f;
#pragma unroll
    for (int i = 0; i < 8; i++){
        float4 q = p4[i];
        pm[2*i] = q.x; ps[2*i] = q.y; pm[2*i+1] = q.z; ps[2*i+1] = q.w;
        mx = fmaxf(mx, fmaxf(q.x, q.z));
    }
    float s = 0.f;
#pragma unroll
    for (int i = 0; i < 16; i++) s += ps[i]*__expf(pm[i] - mx);
    g_lse[g] = mx + __logf(s);
}

// ================= K5: out[row, c] -= lse[row] (streaming hints) =================
__global__ __launch_bounds__(256) void sub_k(float* __restrict__ out){
    const size_t i = (size_t)blockIdx.x*256 + threadIdx.x;   // float4 index
    const float l = __ldg(g_lse + (i >> 8));
    float4 v = __ldcs((const float4*)out + i);
    v.x -= l; v.y -= l; v.z -= l; v.w -= l;
    __stcs((float4*)out + i, v);
}

// ================= launch =================
extern "C" void kernel_launch(void* const* d_in, const int* in_sizes, int n_in,
                              void* d_out, int out_size){
    (void)in_sizes; (void)n_in; (void)out_size;
    const float* enc = (const float*)d_in[0];
    const float* dec = (const float*)d_in[1];
    const float* w1  = (const float*)d_in[2];
    const float* b1  = (const float*)d_in[3];
    const float* w2  = (const float*)d_in[4];
    const float* b2  = (const float*)d_in[5];
    float* out = (float*)d_out;

    cudaFuncSetAttribute(joint_k, cudaFuncAttributeMaxDynamicSharedMemorySize, 65536);

    cvtw2b_k<<<(Cdim*Ddim/8)/256, 256>>>(w2);
    fc1_k<<<dim3(8, 16), 256>>>(enc, w1, 0,    0);   // he
    fc1_k<<<dim3(8, 8),  256>>>(dec, w1, Ddim, 1);   // hd
    tanh_k<<<Bdim*Mdim, 256>>>(b1);
    joint_k<<<4096, 256, 65536>>>(b2, out);
    lse_k<<<ROWS/256, 256>>>();
    sub_k<<<(ROWS*(Cdim/4))/256, 256>>>(out);
}

// round 9
// speedup vs baseline: 1.3212x; 1.0688x over previous
#include <cuda_runtime.h>
#include <cuda_bf16.h>
#include <cstdint>

// Problem dims
#define Bdim 4
#define Mdim 256
#define Ndim 128
#define Ddim 512
#define Cdim 1024
#define ROWS (Bdim*Mdim*Ndim)   // 131072

// -------- scratch (device globals) --------
__device__ float g_he[Bdim*Mdim*Ddim];          // 2 MB
__device__ float g_hd[Bdim*Ndim*Ddim];          // 1 MB
__device__ __nv_bfloat16 g_w2b[Cdim*Ddim];      // 1 MB   w2 -> bf16
__device__ __nv_bfloat16 g_H[(size_t)ROWS*Ddim];// 134 MB H = tanh(...) bf16
__device__ float g_part[(size_t)ROWS*32];       // 16 MB (max,sum) x16 per row
__device__ float g_lse[ROWS];                   // 0.5 MB

// -------- helpers --------
__device__ __forceinline__ float tanh_fast(float x){
    float r; asm("tanh.approx.f32 %0, %1;" : "=f"(r) : "f"(x)); return r;
}
__device__ __forceinline__ unsigned pk(float lo, float hi){
    unsigned r;
    asm("cvt.rn.bf16x2.f32 %0, %2, %1;" : "=r"(r) : "f"(lo), "f"(hi));
    return r;
}
__device__ __forceinline__ void mma_bf16(float* d, const unsigned* a, const unsigned* b){
    asm volatile(
        "mma.sync.aligned.m16n8k16.row.col.f32.bf16.bf16.f32 "
        "{%0,%1,%2,%3}, {%4,%5,%6,%7}, {%8,%9}, {%0,%1,%2,%3};\n"
        : "+f"(d[0]), "+f"(d[1]), "+f"(d[2]), "+f"(d[3])
        : "r"(a[0]), "r"(a[1]), "r"(a[2]), "r"(a[3]), "r"(b[0]), "r"(b[1]));
}
__device__ __forceinline__ unsigned smem_u32(const void* p){
    unsigned a;
    asm("{ .reg .u64 t; cvta.to.shared.u64 t, %1; cvt.u32.u64 %0, t; }" : "=r"(a) : "l"(p));
    return a;
}
__device__ __forceinline__ void cpa16(unsigned saddr, const void* g){
    asm volatile("cp.async.cg.shared.global [%0], [%1], 16;" :: "r"(saddr), "l"(g));
}
#define CPA_COMMIT() asm volatile("cp.async.commit_group;" ::: "memory")
#define CPA_WAIT0()  asm volatile("cp.async.wait_group 0;" ::: "memory")
#define CPA_WAIT1()  asm volatile("cp.async.wait_group 1;" ::: "memory")

// ================= K0: w2 -> bf16 =================
__global__ __launch_bounds__(256) void cvtw2b_k(const float* __restrict__ w2){
    const int i = blockIdx.x*256 + threadIdx.x;
    float4 v0 = ((const float4*)w2)[2*i];
    float4 v1 = ((const float4*)w2)[2*i + 1];
    uint4 o;
    o.x = pk(v0.x, v0.y); o.y = pk(v0.z, v0.w);
    o.z = pk(v1.x, v1.y); o.w = pk(v1.z, v1.w);
    ((uint4*)g_w2b)[i] = o;
}

// ================= K1: fc1 small GEMMs (fp32, exact) =================
__global__ __launch_bounds__(256) void fc1_k(const float* __restrict__ X,
                                             const float* __restrict__ W,
                                             int woff, int which){
    __shared__ float sX[16][64];
    __shared__ float sW[16][64];
    float* __restrict__ Y = which ? g_hd : g_he;
    const int t  = threadIdx.x;
    const int tx = t & 15, ty = t >> 4;
    const int rb = blockIdx.y << 6, eb = blockIdx.x << 6;
    const int r  = t >> 2, kq = (t & 3) << 2;

    float acc[4][4];
#pragma unroll
    for (int i = 0; i < 4; i++)
#pragma unroll
        for (int j = 0; j < 4; j++) acc[i][j] = 0.f;

    for (int k0 = 0; k0 < Ddim; k0 += 16){
        float4 xv = *(const float4*)(X + (rb + r)*Ddim + k0 + kq);
        float4 wv = *(const float4*)(W + (eb + r)*(2*Ddim) + woff + k0 + kq);
        __syncthreads();
        sX[kq+0][r] = xv.x; sX[kq+1][r] = xv.y; sX[kq+2][r] = xv.z; sX[kq+3][r] = xv.w;
        sW[kq+0][r] = wv.x; sW[kq+1][r] = wv.y; sW[kq+2][r] = wv.z; sW[kq+3][r] = wv.w;
        __syncthreads();
#pragma unroll
        for (int k = 0; k < 16; k++){
            float4 a  = *(const float4*)&sX[k][ty << 2];
            float4 bv = *(const float4*)&sW[k][tx << 2];
            float av[4] = {a.x, a.y, a.z, a.w};
            float bb[4] = {bv.x, bv.y, bv.z, bv.w};
#pragma unroll
            for (int i = 0; i < 4; i++)
#pragma unroll
                for (int j = 0; j < 4; j++) acc[i][j] = fmaf(av[i], bb[j], acc[i][j]);
        }
    }
#pragma unroll
    for (int i = 0; i < 4; i++)
#pragma unroll
        for (int j = 0; j < 4; j++)
            Y[(rb + (ty<<2) + i)*Ddim + eb + (tx<<2) + j] = acc[i][j];
}

// ================= K2: H = bf16(tanh(he + hd + b1)), computed ONCE ============
__global__ __launch_bounds__(256) void tanh_k(const float* __restrict__ b1){
    __shared__ float sHE[512];
    const int bm = blockIdx.x;          // 0..1023
    const int b  = bm >> 8;
    const int t  = threadIdx.x;
    if (t < 128){
        float4 h  = ((const float4*)(g_he + bm*Ddim))[t];
        float4 bb = ((const float4*)b1)[t];
        float4 v; v.x=h.x+bb.x; v.y=h.y+bb.y; v.z=h.z+bb.z; v.w=h.w+bb.w;
        ((float4*)sHE)[t] = v;
    }
    __syncthreads();
    const float* hdB = g_hd + ((size_t)b << 16);
    __nv_bfloat16* Hb = g_H + ((size_t)bm << 16);
#pragma unroll 4
    for (int i = t; i < 128*64; i += 256){
        const int n = i >> 6;
        const int k = (i & 63) << 3;
        float4 d0 = *(const float4*)(hdB + n*Ddim + k);
        float4 d1 = *(const float4*)(hdB + n*Ddim + k + 4);
        float4 h0 = *(const float4*)(sHE + k);
        float4 h1 = *(const float4*)(sHE + k + 4);
        uint4 o;
        o.x = pk(tanh_fast(h0.x + d0.x), tanh_fast(h0.y + d0.y));
        o.y = pk(tanh_fast(h0.z + d0.z), tanh_fast(h0.w + d0.w));
        o.z = pk(tanh_fast(h1.x + d1.x), tanh_fast(h1.y + d1.y));
        o.w = pk(tanh_fast(h1.z + d1.z), tanh_fast(h1.w + d1.w));
        *(uint4*)(Hb + n*Ddim + k) = o;
    }
}

// ================= K3: bf16 GEMM C = H x w2^T ==================================
// CTA: 256 rows x 128 cols, K=512 in 8 chunks of 64. cp.async producer.
// 8 warps as 4(m) x 2(n), warp tile 64x64, mma m16n8k16 bf16.
// smem: sA 2 bufs x 256 rows x 144B, sB 2 bufs x 128 rows x 144B (= 110592 B)
#define PITCH   144
#define A_BUF   36864
#define SB_OFF  73728
#define B_BUF   18432

__global__ __launch_bounds__(256,1) void joint_k(const float* __restrict__ b2,
                                                 float* __restrict__ out){
    extern __shared__ __align__(128) char smemc[];
    const unsigned sb = smem_u32(smemc);

    const int bid = blockIdx.x;
    const int bm2 = bid >> 3;       // 0..511  (256-row block)
    const int ci  = bid & 7;        // 0..7    (128-col block)
    const int t   = threadIdx.x;
    const int w   = t >> 5, l = t & 31;
    const int wm  = w >> 1, wn = w & 1;
    const int lq  = l >> 2, lr = l & 3;
    const int g0  = bm2 << 8;

    // producer mapping: 8 threads cover one 128B row-chunk
    const int prr = t >> 3;         // 0..31: base row
    const int pcc = (t & 7) << 4;   // byte col within 128B row chunk

    const char* aGp = (const char*)(g_H + (size_t)(g0 + prr)*Ddim) + pcc;
    const char* bGp = (const char*)(g_w2b + (size_t)((ci << 7) + prr)*Ddim) + pcc;
    const unsigned sAp = sb + prr*PITCH + pcc;
    const unsigned sBp = sb + SB_OFF + prr*PITCH + pcc;

    float acc[4][8][4];
#pragma unroll
    for (int mt = 0; mt < 4; mt++)
#pragma unroll
        for (int nt = 0; nt < 8; nt++)
#pragma unroll
            for (int i = 0; i < 4; i++) acc[mt][nt][i] = 0.f;

    // ---- prologue: copy chunk 0 into buf 0 ----
#pragma unroll
    for (int j = 0; j < 8; j++)
        cpa16(sAp + (j << 5)*PITCH, aGp + (size_t)(j << 5)*Ddim*2);
#pragma unroll
    for (int j = 0; j < 4; j++)
        cpa16(sBp + (j << 5)*PITCH, bGp + (size_t)(j << 5)*Ddim*2);
    CPA_COMMIT();

    int buf = 0;
#pragma unroll 1
    for (int kc = 0; kc < 8; kc++){
        // issue copy of chunk kc+1 into the other buffer (overlaps this chunk's mma)
        if (kc < 7){
            const unsigned dst = (buf ^ 1)*1u;
            const unsigned dA = sAp + dst*A_BUF;
            const unsigned dB = sBp + dst*B_BUF;
            const int ko = (kc + 1) << 7;    // 128 bytes per 64-k chunk
#pragma unroll
            for (int j = 0; j < 8; j++)
                cpa16(dA + (j << 5)*PITCH, aGp + (size_t)(j << 5)*Ddim*2 + ko);
#pragma unroll
            for (int j = 0; j < 4; j++)
                cpa16(dB + (j << 5)*PITCH, bGp + (size_t)(j << 5)*Ddim*2 + ko);
            CPA_COMMIT();
            CPA_WAIT1();      // chunk kc complete (chunk kc+1 may be in flight)
        } else {
            CPA_WAIT0();
        }
        __syncthreads();      // chunk kc visible to all warps

        // mma over chunk kc (4 k16 steps)
        const char* A  = smemc + buf*A_BUF;
        const char* Bm = smemc + SB_OFF + buf*B_BUF;
#pragma unroll
        for (int s = 0; s < 4; s++){
            const int off = (s << 5) + (lr << 2);
            unsigned af[4][4], bf[8][2];
#pragma unroll
            for (int mt = 0; mt < 4; mt++){
                const char* ap = A + ((wm << 6) + (mt << 4) + lq)*PITCH + off;
                af[mt][0] = *(const unsigned*)ap;
                af[mt][1] = *(const unsigned*)(ap + 8*PITCH);
                af[mt][2] = *(const unsigned*)(ap + 16);
                af[mt][3] = *(const unsigned*)(ap + 8*PITCH + 16);
            }
#pragma unroll
            for (int nt = 0; nt < 8; nt++){
                const char* bp = Bm + ((wn << 6) + (nt << 3) + lq)*PITCH + off;
                bf[nt][0] = *(const unsigned*)bp;
                bf[nt][1] = *(const unsigned*)(bp + 16);
            }
#pragma unroll
            for (int mt = 0; mt < 4; mt++)
#pragma unroll
                for (int nt = 0; nt < 8; nt++)
                    mma_bf16(acc[mt][nt], af[mt], bf[nt]);
        }
        __syncthreads();      // all warps done reading buf before it is overwritten
        buf ^= 1;
    }

    // ---- epilogue: +b2, store logits, per-row online (max, sumexp) partials ----
    const int colb = (ci << 7) + (wn << 6);
#pragma unroll
    for (int mt = 0; mt < 4; mt++){
#pragma unroll
        for (int h = 0; h < 2; h++){
            const int r = (wm << 6) + (mt << 4) + lq + (h << 3);
            const int g = g0 + r;
            float v[16];
            float mx = -3.4e38f;
#pragma unroll
            for (int nt = 0; nt < 8; nt++){
                const int c = colb + (nt << 3) + (lr << 1);
                float x0 = acc[mt][nt][h*2 + 0] + __ldg(b2 + c);
                float x1 = acc[mt][nt][h*2 + 1] + __ldg(b2 + c + 1);
                v[2*nt] = x0; v[2*nt + 1] = x1;
                mx = fmaxf(mx, fmaxf(x0, x1));
                float2 st; st.x = x0; st.y = x1;
                *(float2*)(out + (size_t)g*Cdim + c) = st;
            }
            mx = fmaxf(mx, __shfl_xor_sync(0xffffffffu, mx, 1));
            mx = fmaxf(mx, __shfl_xor_sync(0xffffffffu, mx, 2));
            float s = 0.f;
#pragma unroll
            for (int i = 0; i < 16; i++) s += __expf(v[i] - mx);
            s += __shfl_xor_sync(0xffffffffu, s, 1);
            s += __shfl_xor_sync(0xffffffffu, s, 2);
            if (lr == 0){
                float2 p; p.x = mx; p.y = s;
                *(float2*)(g_part + (size_t)g*32 + (((ci << 1) + wn) << 1)) = p;
            }
        }
    }
}

// ================= K4: combine 16 partials/row -> lse =================
__global__ __launch_bounds__(256) void lse_k(){
    const int g = blockIdx.x*256 + threadIdx.x;
    const float4* p4 = (const float4*)(g_part + (size_t)g*32);
    float pm[16], ps[16];
    float mx = -3.4e38f;
#pragma unroll
    for (int i = 0; i < 8; i++){
        float4 q = p4[i];
        pm[2*i] = q.x; ps[2*i] = q.y; pm[2*i+1] = q.z; ps[2*i+1] = q.w;
        mx = fmaxf(mx, fmaxf(q.x, q.z));
    }
    float s = 0.f;
#pragma unroll
    for (int i = 0; i < 16; i++) s += ps[i]*__expf(pm[i] - mx);
    g_lse[g] = mx + __logf(s);
}

// ================= K5: out[row, c] -= lse[row] (streaming hints) =================
__global__ __launch_bounds__(256) void sub_k(float* __restrict__ out){
    const size_t i = (size_t)blockIdx.x*256 + threadIdx.x;   // float4 index
    const float l = __ldg(g_lse + (i >> 8));
    float4 v = __ldcs((const float4*)out + i);
    v.x -= l; v.y -= l; v.z -= l; v.w -= l;
    __stcs((float4*)out + i, v);
}

// ================= launch =================
extern "C" void kernel_launch(void* const* d_in, const int* in_sizes, int n_in,
                              void* d_out, int out_size){
    (void)in_sizes; (void)n_in; (void)out_size;
    const float* enc = (const float*)d_in[0];
    const float* dec = (const float*)d_in[1];
    const float* w1  = (const float*)d_in[2];
    const float* b1  = (const float*)d_in[3];
    const float* w2  = (const float*)d_in[4];
    const float* b2  = (const float*)d_in[5];
    float* out = (float*)d_out;

    cudaFuncSetAttribute(joint_k, cudaFuncAttributeMaxDynamicSharedMemorySize, 2*A_BUF + 2*B_BUF);

    cvtw2b_k<<<(Cdim*Ddim/8)/256, 256>>>(w2);
    fc1_k<<<dim3(8, 16), 256>>>(enc, w1, 0,    0);   // he
    fc1_k<<<dim3(8, 8),  256>>>(dec, w1, Ddim, 1);   // hd
    tanh_k<<<Bdim*Mdim, 256>>>(b1);
    joint_k<<<4096, 256, 2*A_BUF + 2*B_BUF>>>(b2, out);
    lse_k<<<ROWS/256, 256>>>();
    sub_k<<<(ROWS*(Cdim/4))/256, 256>>>(out);
}

// round 10
// speedup vs baseline: 1.5434x; 1.1682x over previous
#include <cuda_runtime.h>
#include <cuda_bf16.h>
#include <cstdint>

// Problem dims
#define Bdim 4
#define Mdim 256
#define Ndim 128
#define Ddim 512
#define Cdim 1024
#define ROWS (Bdim*Mdim*Ndim)   // 131072

// -------- scratch (device globals) --------
__device__ float g_he[Bdim*Mdim*Ddim];          // 2 MB
__device__ float g_hd[Bdim*Ndim*Ddim];          // 1 MB
__device__ __nv_bfloat16 g_w2b[Cdim*Ddim];      // 1 MB   w2 -> bf16
__device__ __nv_bfloat16 g_H[(size_t)ROWS*Ddim];// 134 MB H = tanh(...) bf16

// -------- helpers --------
__device__ __forceinline__ float tanh_fast(float x){
    float r; asm("tanh.approx.f32 %0, %1;" : "=f"(r) : "f"(x)); return r;
}
__device__ __forceinline__ unsigned pk(float lo, float hi){
    unsigned r;
    asm("cvt.rn.bf16x2.f32 %0, %2, %1;" : "=r"(r) : "f"(lo), "f"(hi));
    return r;
}
__device__ __forceinline__ void mma_bf16(float* d, const unsigned* a, const unsigned* b){
    asm volatile(
        "mma.sync.aligned.m16n8k16.row.col.f32.bf16.bf16.f32 "
        "{%0,%1,%2,%3}, {%4,%5,%6,%7}, {%8,%9}, {%0,%1,%2,%3};\n"
        : "+f"(d[0]), "+f"(d[1]), "+f"(d[2]), "+f"(d[3])
        : "r"(a[0]), "r"(a[1]), "r"(a[2]), "r"(a[3]), "r"(b[0]), "r"(b[1]));
}
__device__ __forceinline__ unsigned smem_u32(const void* p){
    unsigned a;
    asm("{ .reg .u64 t; cvta.to.shared.u64 t, %1; cvt.u32.u64 %0, t; }" : "=r"(a) : "l"(p));
    return a;
}
__device__ __forceinline__ void cpa16(unsigned saddr, const void* g){
    asm volatile("cp.async.cg.shared.global [%0], [%1], 16;" :: "r"(saddr), "l"(g));
}
#define CPA_COMMIT() asm volatile("cp.async.commit_group;" ::: "memory")
#define CPA_WAIT0()  asm volatile("cp.async.wait_group 0;" ::: "memory")
#define CPA_WAIT1()  asm volatile("cp.async.wait_group 1;" ::: "memory")

// ================= K0: w2 -> bf16 =================
__global__ __launch_bounds__(256) void cvtw2b_k(const float* __restrict__ w2){
    const int i = blockIdx.x*256 + threadIdx.x;
    float4 v0 = ((const float4*)w2)[2*i];
    float4 v1 = ((const float4*)w2)[2*i + 1];
    uint4 o;
    o.x = pk(v0.x, v0.y); o.y = pk(v0.z, v0.w);
    o.z = pk(v1.x, v1.y); o.w = pk(v1.z, v1.w);
    ((uint4*)g_w2b)[i] = o;
}

// ================= K1: fc1 small GEMMs (fp32, exact) =================
__global__ __launch_bounds__(256) void fc1_k(const float* __restrict__ X,
                                             const float* __restrict__ W,
                                             int woff, int which){
    __shared__ float sX[16][64];
    __shared__ float sW[16][64];
    float* __restrict__ Y = which ? g_hd : g_he;
    const int t  = threadIdx.x;
    const int tx = t & 15, ty = t >> 4;
    const int rb = blockIdx.y << 6, eb = blockIdx.x << 6;
    const int r  = t >> 2, kq = (t & 3) << 2;

    float acc[4][4];
#pragma unroll
    for (int i = 0; i < 4; i++)
#pragma unroll
        for (int j = 0; j < 4; j++) acc[i][j] = 0.f;

    for (int k0 = 0; k0 < Ddim; k0 += 16){
        float4 xv = *(const float4*)(X + (rb + r)*Ddim + k0 + kq);
        float4 wv = *(const float4*)(W + (eb + r)*(2*Ddim) + woff + k0 + kq);
        __syncthreads();
        sX[kq+0][r] = xv.x; sX[kq+1][r] = xv.y; sX[kq+2][r] = xv.z; sX[kq+3][r] = xv.w;
        sW[kq+0][r] = wv.x; sW[kq+1][r] = wv.y; sW[kq+2][r] = wv.z; sW[kq+3][r] = wv.w;
        __syncthreads();
#pragma unroll
        for (int k = 0; k < 16; k++){
            float4 a  = *(const float4*)&sX[k][ty << 2];
            float4 bv = *(const float4*)&sW[k][tx << 2];
            float av[4] = {a.x, a.y, a.z, a.w};
            float bb[4] = {bv.x, bv.y, bv.z, bv.w};
#pragma unroll
            for (int i = 0; i < 4; i++)
#pragma unroll
                for (int j = 0; j < 4; j++) acc[i][j] = fmaf(av[i], bb[j], acc[i][j]);
        }
    }
#pragma unroll
    for (int i = 0; i < 4; i++)
#pragma unroll
        for (int j = 0; j < 4; j++)
            Y[(rb + (ty<<2) + i)*Ddim + eb + (tx<<2) + j] = acc[i][j];
}

// ================= K2: H = bf16(tanh(he + hd + b1)), computed ONCE ============
__global__ __launch_bounds__(256) void tanh_k(const float* __restrict__ b1){
    __shared__ float sHE[512];
    const int bm = blockIdx.x;          // 0..1023
    const int b  = bm >> 8;
    const int t  = threadIdx.x;
    if (t < 128){
        float4 h  = ((const float4*)(g_he + bm*Ddim))[t];
        float4 bb = ((const float4*)b1)[t];
        float4 v; v.x=h.x+bb.x; v.y=h.y+bb.y; v.z=h.z+bb.z; v.w=h.w+bb.w;
        ((float4*)sHE)[t] = v;
    }
    __syncthreads();
    const float* hdB = g_hd + ((size_t)b << 16);
    __nv_bfloat16* Hb = g_H + ((size_t)bm << 16);
#pragma unroll 4
    for (int i = t; i < 128*64; i += 256){
        const int n = i >> 6;
        const int k = (i & 63) << 3;
        float4 d0 = *(const float4*)(hdB + n*Ddim + k);
        float4 d1 = *(const float4*)(hdB + n*Ddim + k + 4);
        float4 h0 = *(const float4*)(sHE + k);
        float4 h1 = *(const float4*)(sHE + k + 4);
        uint4 o;
        o.x = pk(tanh_fast(h0.x + d0.x), tanh_fast(h0.y + d0.y));
        o.y = pk(tanh_fast(h0.z + d0.z), tanh_fast(h0.w + d0.w));
        o.z = pk(tanh_fast(h1.x + d1.x), tanh_fast(h1.y + d1.y));
        o.w = pk(tanh_fast(h1.z + d1.z), tanh_fast(h1.w + d1.w));
        *(uint4*)(Hb + n*Ddim + k) = o;
    }
}

// ================= K3: fused GEMM + log-softmax ================================
// One CTA per bm (grid 1024): 128 rows x ALL 1024 cols. 4 col-passes of 256.
// K=512 in 8 chunks of 64. A (128x512 bf16) resident in smem for all passes.
// 8 warps as 2(m) x 4(n), warp tile 64x64 (identical mma code to R9).
// smem: sA 8 chunks x 128 rows x 144B = 147456
//       sB 2 bufs x 256 rows x 144B  =  73728   (total 221184)
// reduction area reuses sB after GEMM.
#define PITCH   144
#define ACHUNK  18432
#define SB_OFF  147456
#define B_BUF   36864
#define SMEM_TOT 221184

__global__ __launch_bounds__(256,1) void fused_k(const float* __restrict__ b2,
                                                 float* __restrict__ out){
    extern __shared__ __align__(128) char smemc[];
    const unsigned sb = smem_u32(smemc);

    const int bm  = blockIdx.x;     // 0..1023
    const int g0  = bm << 7;        // first global row
    const int t   = threadIdx.x;
    const int w   = t >> 5, l = t & 31;
    const int wm  = w >> 2, wn = w & 3;
    const int lq  = l >> 2, lr = l & 3;

    // producer mapping: 8 threads per 128B row chunk, base row t>>3, stride 32
    const int pr  = t >> 3;
    const int pc  = (t & 7) << 4;
    const char* aG = (const char*)(g_H + ((size_t)(g0 + pr) << 9)) + pc;
    const char* bG = (const char*)g_w2b + ((size_t)pr << 10) + pc;
    const unsigned sAp = sb + pr*PITCH + pc;
    const unsigned sBp = sb + SB_OFF + pr*PITCH + pc;

    float m8[8], s8[8];
#pragma unroll
    for (int i = 0; i < 8; i++){ m8[i] = -3.4e38f; s8[i] = 0.f; }

    float acc[4][8][4];

    // prologue: A chunk 0 + B(pass0, chunk0) -> buf 0
#pragma unroll
    for (int j = 0; j < 4; j++)
        cpa16(sAp + (j << 5)*PITCH, aG + ((size_t)(j << 5) << 10));
#pragma unroll
    for (int j = 0; j < 8; j++)
        cpa16(sBp + (j << 5)*PITCH, bG + ((size_t)(j << 5) << 10));
    CPA_COMMIT();

#pragma unroll 1
    for (int q = 0; q < 32; q++){
        const int pass = q >> 3, kc = q & 7, buf = q & 1;
        // issue copies for q+1 (overlap with this chunk's mma)
        if (q < 31){
            const int qn = q + 1, pn = qn >> 3, kn = qn & 7;
            if (qn < 8){
#pragma unroll
                for (int j = 0; j < 4; j++)
                    cpa16(sAp + kn*ACHUNK + (j << 5)*PITCH,
                          aG + ((size_t)(j << 5) << 10) + (kn << 7));
            }
            const char* bsrc = bG + ((size_t)(pn << 8) << 10) + (kn << 7);
            const unsigned bdst = sBp + (qn & 1)*B_BUF;
#pragma unroll
            for (int j = 0; j < 8; j++)
                cpa16(bdst + (j << 5)*PITCH, bsrc + ((size_t)(j << 5) << 10));
            CPA_COMMIT();
            CPA_WAIT1();
        } else {
            CPA_WAIT0();
        }
        __syncthreads();

        if (kc == 0){
#pragma unroll
            for (int mt = 0; mt < 4; mt++)
#pragma unroll
                for (int nt = 0; nt < 8; nt++)
#pragma unroll
                    for (int i = 0; i < 4; i++) acc[mt][nt][i] = 0.f;
        }

        // mma over chunk kc (4 k16 steps) — identical addressing to R9
        const char* A  = smemc + kc*ACHUNK;
        const char* Bm = smemc + SB_OFF + buf*B_BUF;
#pragma unroll
        for (int s = 0; s < 4; s++){
            const int off = (s << 5) + (lr << 2);
            unsigned af[4][4], bf[8][2];
#pragma unroll
            for (int mt = 0; mt < 4; mt++){
                const char* ap = A + ((wm << 6) + (mt << 4) + lq)*PITCH + off;
                af[mt][0] = *(const unsigned*)ap;
                af[mt][1] = *(const unsigned*)(ap + 8*PITCH);
                af[mt][2] = *(const unsigned*)(ap + 16);
                af[mt][3] = *(const unsigned*)(ap + 8*PITCH + 16);
            }
#pragma unroll
            for (int nt = 0; nt < 8; nt++){
                const char* bp = Bm + ((wn << 6) + (nt << 3) + lq)*PITCH + off;
                bf[nt][0] = *(const unsigned*)bp;
                bf[nt][1] = *(const unsigned*)(bp + 16);
            }
#pragma unroll
            for (int mt = 0; mt < 4; mt++)
#pragma unroll
                for (int nt = 0; nt < 8; nt++)
                    mma_bf16(acc[mt][nt], af[mt], bf[nt]);
        }

        // pass epilogue: +b2, write logits, merge online (max, sumexp)
        if (kc == 7){
            const int colb = (pass << 8) + (wn << 6);
#pragma unroll
            for (int mt = 0; mt < 4; mt++){
#pragma unroll
                for (int h = 0; h < 2; h++){
                    const int r = (wm << 6) + (mt << 4) + lq + (h << 3);
                    const int g = g0 + r;
                    float v[16];
                    float gm = -3.4e38f;
#pragma unroll
                    for (int nt = 0; nt < 8; nt++){
                        const int c = colb + (nt << 3) + (lr << 1);
                        float x0 = acc[mt][nt][h*2 + 0] + __ldg(b2 + c);
                        float x1 = acc[mt][nt][h*2 + 1] + __ldg(b2 + c + 1);
                        v[2*nt] = x0; v[2*nt + 1] = x1;
                        gm = fmaxf(gm, fmaxf(x0, x1));
                        float2 st; st.x = x0; st.y = x1;
                        *(float2*)(out + (size_t)g*Cdim + c) = st;
                    }
                    float gs = 0.f;
#pragma unroll
                    for (int i = 0; i < 16; i++) gs += __expf(v[i] - gm);
                    const int slot = (mt << 1) + h;
                    float mn = fmaxf(m8[slot], gm);
                    s8[slot] = s8[slot]*__expf(m8[slot] - mn) + gs*__expf(gm - mn);
                    m8[slot] = mn;
                }
            }
        }
        __syncthreads();
    }

    // ---- cross-lane (lr) then cross-warp (wn) reduction of (m, s) ----
#pragma unroll
    for (int i = 0; i < 8; i++){
#pragma unroll
        for (int k = 1; k <= 2; k <<= 1){
            float om = __shfl_xor_sync(0xffffffffu, m8[i], k);
            float os = __shfl_xor_sync(0xffffffffu, s8[i], k);
            float mn = fmaxf(m8[i], om);
            s8[i] = s8[i]*__expf(m8[i] - mn) + os*__expf(om - mn);
            m8[i] = mn;
        }
    }
    float* sred = (float*)(smemc + SB_OFF);          // [128][4] float2
    float* slse = (float*)(smemc + SB_OFF + 4096);   // [128]
    if (lr == 0){
#pragma unroll
        for (int i = 0; i < 8; i++){
            const int r = (wm << 6) + ((i >> 1) << 4) + lq + ((i & 1) << 3);
            float2 p; p.x = m8[i]; p.y = s8[i];
            *(float2*)(sred + ((r << 2) + wn)*2) = p;
        }
    }
    __syncthreads();
    if (t < 128){
        const float2* p = (const float2*)(sred + (t << 3));
        float2 q0 = p[0], q1 = p[1], q2 = p[2], q3 = p[3];
        float mx = fmaxf(fmaxf(q0.x, q1.x), fmaxf(q2.x, q3.x));
        float s  = q0.y*__expf(q0.x - mx) + q1.y*__expf(q1.x - mx)
                 + q2.y*__expf(q2.x - mx) + q3.y*__expf(q3.x - mx);
        slse[t] = mx + __logf(s);
    }
    __syncthreads();

    // ---- final: out -= lse (tile is L2-hot) ----
    float4* outB = (float4*)out + ((size_t)g0 << 8);   // 256 float4 per row
#pragma unroll 4
    for (int i = t; i < 128*256; i += 256){
        const float lse = slse[i >> 8];
        float4 v = outB[i];
        v.x -= lse; v.y -= lse; v.z -= lse; v.w -= lse;
        __stcs(outB + i, v);
    }
}

// ================= launch =================
extern "C" void kernel_launch(void* const* d_in, const int* in_sizes, int n_in,
                              void* d_out, int out_size){
    (void)in_sizes; (void)n_in; (void)out_size;
    const float* enc = (const float*)d_in[0];
    const float* dec = (const float*)d_in[1];
    const float* w1  = (const float*)d_in[2];
    const float* b1  = (const float*)d_in[3];
    const float* w2  = (const float*)d_in[4];
    const float* b2  = (const float*)d_in[5];
    float* out = (float*)d_out;

    cudaFuncSetAttribute(fused_k, cudaFuncAttributeMaxDynamicSharedMemorySize, SMEM_TOT);

    cvtw2b_k<<<(Cdim*Ddim/8)/256, 256>>>(w2);
    fc1_k<<<dim3(8, 16), 256>>>(enc, w1, 0,    0);   // he
    fc1_k<<<dim3(8, 8),  256>>>(dec, w1, Ddim, 1);   // hd
    tanh_k<<<Bdim*Mdim, 256>>>(b1);
    fused_k<<<1024, 256, SMEM_TOT>>>(b2, out);
}

// round 11
// speedup vs baseline: 1.6115x; 1.0442x over previous
#include <cuda_runtime.h>
#include <cuda_bf16.h>
#include <cstdint>

// Problem dims
#define Bdim 4
#define Mdim 256
#define Ndim 128
#define Ddim 512
#define Cdim 1024
#define ROWS (Bdim*Mdim*Ndim)   // 131072

// -------- scratch (device globals) --------
__device__ float g_he[Bdim*Mdim*Ddim];          // 2 MB
__device__ float g_hd[Bdim*Ndim*Ddim];          // 1 MB
__device__ __nv_bfloat16 g_w2b[Cdim*Ddim];      // 1 MB   w2 -> bf16

// -------- helpers --------
__device__ __forceinline__ float tanh_fast(float x){
    float r; asm("tanh.approx.f32 %0, %1;" : "=f"(r) : "f"(x)); return r;
}
__device__ __forceinline__ unsigned pk(float lo, float hi){
    unsigned r;
    asm("cvt.rn.bf16x2.f32 %0, %2, %1;" : "=r"(r) : "f"(lo), "f"(hi));
    return r;
}
__device__ __forceinline__ void mma_bf16(float* d, const unsigned* a, const unsigned* b){
    asm volatile(
        "mma.sync.aligned.m16n8k16.row.col.f32.bf16.bf16.f32 "
        "{%0,%1,%2,%3}, {%4,%5,%6,%7}, {%8,%9}, {%0,%1,%2,%3};\n"
        : "+f"(d[0]), "+f"(d[1]), "+f"(d[2]), "+f"(d[3])
        : "r"(a[0]), "r"(a[1]), "r"(a[2]), "r"(a[3]), "r"(b[0]), "r"(b[1]));
}
__device__ __forceinline__ unsigned smem_u32(const void* p){
    unsigned a;
    asm("{ .reg .u64 t; cvta.to.shared.u64 t, %1; cvt.u32.u64 %0, t; }" : "=r"(a) : "l"(p));
    return a;
}
__device__ __forceinline__ void cpa16(unsigned saddr, const void* g){
    asm volatile("cp.async.cg.shared.global [%0], [%1], 16;" :: "r"(saddr), "l"(g));
}
#define CPA_COMMIT() asm volatile("cp.async.commit_group;" ::: "memory")
#define CPA_WAIT0()  asm volatile("cp.async.wait_group 0;" ::: "memory")

// ================= K0: w2 -> bf16 =================
__global__ __launch_bounds__(256) void cvtw2b_k(const float* __restrict__ w2){
    const int i = blockIdx.x*256 + threadIdx.x;
    float4 v0 = ((const float4*)w2)[2*i];
    float4 v1 = ((const float4*)w2)[2*i + 1];
    uint4 o;
    o.x = pk(v0.x, v0.y); o.y = pk(v0.z, v0.w);
    o.z = pk(v1.x, v1.y); o.w = pk(v1.z, v1.w);
    ((uint4*)g_w2b)[i] = o;
}

// ================= K1: fc1 small GEMMs (fp32, exact) =================
__global__ __launch_bounds__(256) void fc1_k(const float* __restrict__ X,
                                             const float* __restrict__ W,
                                             int woff, int which){
    __shared__ float sX[16][64];
    __shared__ float sW[16][64];
    float* __restrict__ Y = which ? g_hd : g_he;
    const int t  = threadIdx.x;
    const int tx = t & 15, ty = t >> 4;
    const int rb = blockIdx.y << 6, eb = blockIdx.x << 6;
    const int r  = t >> 2, kq = (t & 3) << 2;

    float acc[4][4];
#pragma unroll
    for (int i = 0; i < 4; i++)
#pragma unroll
        for (int j = 0; j < 4; j++) acc[i][j] = 0.f;

    for (int k0 = 0; k0 < Ddim; k0 += 16){
        float4 xv = *(const float4*)(X + (rb + r)*Ddim + k0 + kq);
        float4 wv = *(const float4*)(W + (eb + r)*(2*Ddim) + woff + k0 + kq);
        __syncthreads();
        sX[kq+0][r] = xv.x; sX[kq+1][r] = xv.y; sX[kq+2][r] = xv.z; sX[kq+3][r] = xv.w;
        sW[kq+0][r] = wv.x; sW[kq+1][r] = wv.y; sW[kq+2][r] = wv.z; sW[kq+3][r] = wv.w;
        __syncthreads();
#pragma unroll
        for (int k = 0; k < 16; k++){
            float4 a  = *(const float4*)&sX[k][ty << 2];
            float4 bv = *(const float4*)&sW[k][tx << 2];
            float av[4] = {a.x, a.y, a.z, a.w};
            float bb[4] = {bv.x, bv.y, bv.z, bv.w};
#pragma unroll
            for (int i = 0; i < 4; i++)
#pragma unroll
                for (int j = 0; j < 4; j++) acc[i][j] = fmaf(av[i], bb[j], acc[i][j]);
        }
    }
#pragma unroll
    for (int i = 0; i < 4; i++)
#pragma unroll
        for (int j = 0; j < 4; j++)
            Y[(rb + (ty<<2) + i)*Ddim + eb + (tx<<2) + j] = acc[i][j];
}

// ================= K2: fused tanh + GEMM + log-softmax =========================
// One CTA per bm (grid 1024): 128 rows x ALL 1024 cols. 4 col-passes of 256.
// K=512 in 8 chunks of 64. A produced in-kernel (pass 0) and resident.
// 8 warps as 2(m) x 4(n), warp tile 64x64. 1 sync per chunk, 2 B stages.
// smem: sA 8x18432 = 147456, sB 2x36864 = 73728, sHE 2048  (= 223232)
#define PITCH   144
#define ACHUNK  18432
#define SB_OFF  147456
#define B_BUF   36864
#define SHE_OFF 221184
#define SMEM_TOT 223232

__global__ __launch_bounds__(256,1) void fused_k(const float* __restrict__ b1,
                                                 const float* __restrict__ b2,
                                                 float* __restrict__ out){
    extern __shared__ __align__(128) char smemc[];
    const unsigned sb = smem_u32(smemc);

    const int bm  = blockIdx.x;     // 0..1023
    const int g0  = bm << 7;        // first global row
    const int b   = bm >> 8;        // batch
    const int t   = threadIdx.x;
    const int w   = t >> 5, l = t & 31;
    const int wm  = w >> 2, wn = w & 3;
    const int lq  = l >> 2, lr = l & 3;

    float* sHE = (float*)(smemc + SHE_OFF);

    // B producer mapping: 8 threads per 128B row chunk, rows pr + 32j
    const int pr  = t >> 3;
    const int pc  = (t & 7) << 4;
    const char* bG = (const char*)g_w2b + ((size_t)pr << 10) + pc;
    const unsigned sBp = sb + SB_OFF + pr*PITCH + pc;

    // A producer mapping: rows (t>>4) + 16i, float4 index t&15 in 64-float chunk row
    const int arb = t >> 4;         // 0..15
    const int af4 = t & 15;
    const float* hdB = g_hd + ((size_t)b << 16);

    // he + b1 -> sHE
    if (t < 128){
        float4 h  = ((const float4*)(g_he + (size_t)bm*Ddim))[t];
        float4 bb = ((const float4*)b1)[t];
        float4 v; v.x = h.x+bb.x; v.y = h.y+bb.y; v.z = h.z+bb.z; v.w = h.w+bb.w;
        ((float4*)sHE)[t] = v;
    }
    // B chunk 0 (pass 0) -> stage 0
#pragma unroll
    for (int j = 0; j < 8; j++)
        cpa16(sBp + (j << 5)*PITCH, bG + ((size_t)(j << 5) << 10));
    CPA_COMMIT();
    __syncthreads();      // sHE visible for A production

    float m8[8], s8[8];
#pragma unroll
    for (int i = 0; i < 8; i++){ m8[i] = -3.4e38f; s8[i] = 0.f; }
    float acc[4][8][4];

#pragma unroll 1
    for (int q = 0; q < 32; q++){
        const int pass = q >> 3, kc = q & 7, buf = q & 1;

        // pass 0: produce A chunk q = bf16(tanh(he + b1 + hd)) into resident sA
        if (q < 8){
            char* dA = smemc + q*ACHUNK;
            const float* hesrc = sHE + (q << 6) + (af4 << 2);
            float4 h = *(const float4*)hesrc;
#pragma unroll
            for (int i = 0; i < 8; i++){
                const int row = arb + (i << 4);
                float4 d = *(const float4*)(hdB + (size_t)row*Ddim + (q << 6) + (af4 << 2));
                uint2 o;
                o.x = pk(tanh_fast(h.x + d.x), tanh_fast(h.y + d.y));
                o.y = pk(tanh_fast(h.z + d.z), tanh_fast(h.w + d.w));
                *(uint2*)(dA + row*PITCH + (af4 << 3)) = o;
            }
        }

        CPA_WAIT0();          // B stage q&1 complete (per-thread)
        __syncthreads();      // all copies + A production visible

        // issue B copy for q+1 into the other stage (overlaps mma + epilogue)
        if (q < 31){
            const int qn = q + 1, pn = qn >> 3, kn = qn & 7;
            const char* bsrc = bG + ((size_t)(pn << 8) << 10) + (kn << 7);
            const unsigned bdst = sBp + (qn & 1)*B_BUF;
#pragma unroll
            for (int j = 0; j < 8; j++)
                cpa16(bdst + (j << 5)*PITCH, bsrc + ((size_t)(j << 5) << 10));
            CPA_COMMIT();
        }

        if (kc == 0){
#pragma unroll
            for (int mt = 0; mt < 4; mt++)
#pragma unroll
                for (int nt = 0; nt < 8; nt++)
#pragma unroll
                    for (int i = 0; i < 4; i++) acc[mt][nt][i] = 0.f;
        }

        // mma over chunk kc (4 k16 steps)
        const char* A  = smemc + kc*ACHUNK;
        const char* Bm = smemc + SB_OFF + buf*B_BUF;
#pragma unroll
        for (int s = 0; s < 4; s++){
            const int off = (s << 5) + (lr << 2);
            unsigned af[4][4], bf[8][2];
#pragma unroll
            for (int mt = 0; mt < 4; mt++){
                const char* ap = A + ((wm << 6) + (mt << 4) + lq)*PITCH + off;
                af[mt][0] = *(const unsigned*)ap;
                af[mt][1] = *(const unsigned*)(ap + 8*PITCH);
                af[mt][2] = *(const unsigned*)(ap + 16);
                af[mt][3] = *(const unsigned*)(ap + 8*PITCH + 16);
            }
#pragma unroll
            for (int nt = 0; nt < 8; nt++){
                const char* bp = Bm + ((wn << 6) + (nt << 3) + lq)*PITCH + off;
                bf[nt][0] = *(const unsigned*)bp;
                bf[nt][1] = *(const unsigned*)(bp + 16);
            }
#pragma unroll
            for (int mt = 0; mt < 4; mt++)
#pragma unroll
                for (int nt = 0; nt < 8; nt++)
                    mma_bf16(acc[mt][nt], af[mt], bf[nt]);
        }

        // pass epilogue: +b2, write logits, merge online (max, sumexp)
        if (kc == 7){
            const int colb = (pass << 8) + (wn << 6);
#pragma unroll
            for (int mt = 0; mt < 4; mt++){
#pragma unroll
                for (int h = 0; h < 2; h++){
                    const int r = (wm << 6) + (mt << 4) + lq + (h << 3);
                    const int g = g0 + r;
                    float v[16];
                    float gm = -3.4e38f;
#pragma unroll
                    for (int nt = 0; nt < 8; nt++){
                        const int c = colb + (nt << 3) + (lr << 1);
                        float x0 = acc[mt][nt][h*2 + 0] + __ldg(b2 + c);
                        float x1 = acc[mt][nt][h*2 + 1] + __ldg(b2 + c + 1);
                        v[2*nt] = x0; v[2*nt + 1] = x1;
                        gm = fmaxf(gm, fmaxf(x0, x1));
                        float2 st; st.x = x0; st.y = x1;
                        *(float2*)(out + (size_t)g*Cdim + c) = st;
                    }
                    float gs = 0.f;
#pragma unroll
                    for (int i = 0; i < 16; i++) gs += __expf(v[i] - gm);
                    const int slot = (mt << 1) + h;
                    float mn = fmaxf(m8[slot], gm);
                    s8[slot] = s8[slot]*__expf(m8[slot] - mn) + gs*__expf(gm - mn);
                    m8[slot] = mn;
                }
            }
        }
    }

    // ---- cross-lane (lr) reduction of (m, s) ----
#pragma unroll
    for (int i = 0; i < 8; i++){
#pragma unroll
        for (int k = 1; k <= 2; k <<= 1){
            float om = __shfl_xor_sync(0xffffffffu, m8[i], k);
            float os = __shfl_xor_sync(0xffffffffu, s8[i], k);
            float mn = fmaxf(m8[i], om);
            s8[i] = s8[i]*__expf(m8[i] - mn) + os*__expf(om - mn);
            m8[i] = mn;
        }
    }
    __syncthreads();   // B stages dead; reuse as reduction area
    float* sred = (float*)(smemc + SB_OFF);          // [128][4] float2
    float* slse = (float*)(smemc + SB_OFF + 4096);   // [128]
    if (lr == 0){
#pragma unroll
        for (int i = 0; i < 8; i++){
            const int r = (wm << 6) + ((i >> 1) << 4) + lq + ((i & 1) << 3);
            float2 p; p.x = m8[i]; p.y = s8[i];
            *(float2*)(sred + ((r << 2) + wn)*2) = p;
        }
    }
    __syncthreads();
    if (t < 128){
        const float2* p = (const float2*)(sred + (t << 3));
        float2 q0 = p[0], q1 = p[1], q2 = p[2], q3 = p[3];
        float mx = fmaxf(fmaxf(q0.x, q1.x), fmaxf(q2.x, q3.x));
        float s  = q0.y*__expf(q0.x - mx) + q1.y*__expf(q1.x - mx)
                 + q2.y*__expf(q2.x - mx) + q3.y*__expf(q3.x - mx);
        slse[t] = mx + __logf(s);
    }
    __syncthreads();

    // ---- final: out -= lse (tile is L2-hot) ----
    float4* outB = (float4*)out + ((size_t)g0 << 8);   // 256 float4 per row
#pragma unroll 4
    for (int i = t; i < 128*256; i += 256){
        const float lse = slse[i >> 8];
        float4 v = outB[i];
        v.x -= lse; v.y -= lse; v.z -= lse; v.w -= lse;
        __stcs(outB + i, v);
    }
}

// ================= launch =================
extern "C" void kernel_launch(void* const* d_in, const int* in_sizes, int n_in,
                              void* d_out, int out_size){
    (void)in_sizes; (void)n_in; (void)out_size;
    const float* enc = (const float*)d_in[0];
    const float* dec = (const float*)d_in[1];
    const float* w1  = (const float*)d_in[2];
    const float* b1  = (const float*)d_in[3];
    const float* w2  = (const float*)d_in[4];
    const float* b2  = (const float*)d_in[5];
    float* out = (float*)d_out;

    cudaFuncSetAttribute(fused_k, cudaFuncAttributeMaxDynamicSharedMemorySize, SMEM_TOT);

    cvtw2b_k<<<(Cdim*Ddim/8)/256, 256>>>(w2);
    fc1_k<<<dim3(8, 16), 256>>>(enc, w1, 0,    0);   // he
    fc1_k<<<dim3(8, 8),  256>>>(dec, w1, Ddim, 1);   // hd
    fused_k<<<1024, 256, SMEM_TOT>>>(b1, b2, out);
}

// round 12
// speedup vs baseline: 1.7498x; 1.0858x over previous
#include <cuda_runtime.h>
#include <cuda_bf16.h>
#include <cstdint>

// Problem dims
#define Bdim 4
#define Mdim 256
#define Ndim 128
#define Ddim 512
#define Cdim 1024
#define ROWS (Bdim*Mdim*Ndim)   // 131072

// -------- scratch (device globals) --------
__device__ float g_he[Bdim*Mdim*Ddim];          // 2 MB
__device__ float g_hd[Bdim*Ndim*Ddim];          // 1 MB
__device__ __nv_bfloat16 g_w2b[Cdim*Ddim];      // 1 MB   w2 -> bf16

// -------- helpers --------
__device__ __forceinline__ float tanh_fast(float x){
    float r; asm("tanh.approx.f32 %0, %1;" : "=f"(r) : "f"(x)); return r;
}
__device__ __forceinline__ unsigned pk(float lo, float hi){
    unsigned r;
    asm("cvt.rn.bf16x2.f32 %0, %2, %1;" : "=r"(r) : "f"(lo), "f"(hi));
    return r;
}
__device__ __forceinline__ void mma_bf16(float* d, const unsigned* a, const unsigned* b){
    asm volatile(
        "mma.sync.aligned.m16n8k16.row.col.f32.bf16.bf16.f32 "
        "{%0,%1,%2,%3}, {%4,%5,%6,%7}, {%8,%9}, {%0,%1,%2,%3};\n"
        : "+f"(d[0]), "+f"(d[1]), "+f"(d[2]), "+f"(d[3])
        : "r"(a[0]), "r"(a[1]), "r"(a[2]), "r"(a[3]), "r"(b[0]), "r"(b[1]));
}
__device__ __forceinline__ void ldsm4(unsigned* r, unsigned addr){
    asm volatile("ldmatrix.sync.aligned.m8n8.x4.shared.b16 {%0,%1,%2,%3}, [%4];"
        : "=r"(r[0]), "=r"(r[1]), "=r"(r[2]), "=r"(r[3]) : "r"(addr));
}
__device__ __forceinline__ unsigned smem_u32(const void* p){
    unsigned a;
    asm("{ .reg .u64 t; cvta.to.shared.u64 t, %1; cvt.u32.u64 %0, t; }" : "=r"(a) : "l"(p));
    return a;
}
__device__ __forceinline__ void cpa16(unsigned saddr, const void* g){
    asm volatile("cp.async.cg.shared.global [%0], [%1], 16;" :: "r"(saddr), "l"(g));
}
#define CPA_COMMIT() asm volatile("cp.async.commit_group;" ::: "memory")
#define CPA_WAIT0()  asm volatile("cp.async.wait_group 0;" ::: "memory")

// ================= K0: w2 -> bf16 =================
__global__ __launch_bounds__(256) void cvtw2b_k(const float* __restrict__ w2){
    const int i = blockIdx.x*256 + threadIdx.x;
    float4 v0 = ((const float4*)w2)[2*i];
    float4 v1 = ((const float4*)w2)[2*i + 1];
    uint4 o;
    o.x = pk(v0.x, v0.y); o.y = pk(v0.z, v0.w);
    o.z = pk(v1.x, v1.y); o.w = pk(v1.z, v1.w);
    ((uint4*)g_w2b)[i] = o;
}

// ================= K1: fc1 both GEMMs in one launch (fp32, exact) ==============
// grid (8, 24): by<16 -> he (enc rows), by>=16 -> hd (dec rows)
__global__ __launch_bounds__(256) void fc1_k(const float* __restrict__ enc,
                                             const float* __restrict__ dec,
                                             const float* __restrict__ W){
    __shared__ float sX[16][64];
    __shared__ float sW[16][64];
    const int by = blockIdx.y;
    const int which = (by >= 16);
    const float* __restrict__ X = which ? dec : enc;
    float* __restrict__ Y = which ? g_hd : g_he;
    const int woff = which ? Ddim : 0;
    const int rb = (which ? (by - 16) : by) << 6;
    const int t  = threadIdx.x;
    const int tx = t & 15, ty = t >> 4;
    const int eb = blockIdx.x << 6;
    const int r  = t >> 2, kq = (t & 3) << 2;

    float acc[4][4];
#pragma unroll
    for (int i = 0; i < 4; i++)
#pragma unroll
        for (int j = 0; j < 4; j++) acc[i][j] = 0.f;

    for (int k0 = 0; k0 < Ddim; k0 += 16){
        float4 xv = *(const float4*)(X + (rb + r)*Ddim + k0 + kq);
        float4 wv = *(const float4*)(W + (eb + r)*(2*Ddim) + woff + k0 + kq);
        __syncthreads();
        sX[kq+0][r] = xv.x; sX[kq+1][r] = xv.y; sX[kq+2][r] = xv.z; sX[kq+3][r] = xv.w;
        sW[kq+0][r] = wv.x; sW[kq+1][r] = wv.y; sW[kq+2][r] = wv.z; sW[kq+3][r] = wv.w;
        __syncthreads();
#pragma unroll
        for (int k = 0; k < 16; k++){
            float4 a  = *(const float4*)&sX[k][ty << 2];
            float4 bv = *(const float4*)&sW[k][tx << 2];
            float av[4] = {a.x, a.y, a.z, a.w};
            float bb[4] = {bv.x, bv.y, bv.z, bv.w};
#pragma unroll
            for (int i = 0; i < 4; i++)
#pragma unroll
                for (int j = 0; j < 4; j++) acc[i][j] = fmaf(av[i], bb[j], acc[i][j]);
        }
    }
#pragma unroll
    for (int i = 0; i < 4; i++)
#pragma unroll
        for (int j = 0; j < 4; j++)
            Y[(rb + (ty<<2) + i)*Ddim + eb + (tx<<2) + j] = acc[i][j];
}

// ================= K2: fused tanh + GEMM + log-softmax =========================
// One CTA per bm (grid 1024): 128 rows x ALL 1024 cols. 4 col-passes of 256.
// K=512 in 8 chunks of 64. A produced in-kernel (pass 0) and resident.
// 8 warps as 2(m) x 4(n), warp tile 64x64. ldmatrix fragment loads.
// smem: sA 8x18432 = 147456, sB 2x36864 = 73728, sHE 2048  (= 223232)
#define PITCH   144
#define ACHUNK  18432
#define SB_OFF  147456
#define B_BUF   36864
#define SHE_OFF 221184
#define SMEM_TOT 223232

__global__ __launch_bounds__(256,1) void fused_k(const float* __restrict__ b1,
                                                 const float* __restrict__ b2,
                                                 float* __restrict__ out){
    extern __shared__ __align__(128) char smemc[];
    const unsigned sb = smem_u32(smemc);

    const int bm  = blockIdx.x;     // 0..1023
    const int g0  = bm << 7;        // first global row
    const int b   = bm >> 8;        // batch
    const int t   = threadIdx.x;
    const int w   = t >> 5, l = t & 31;
    const int wm  = w >> 2, wn = w & 3;
    const int lq  = l >> 2, lr = l & 3;

    float* sHE = (float*)(smemc + SHE_OFF);

    // ldmatrix per-lane base offsets
    const unsigned aLane = (unsigned)((l & 15)*PITCH + (l & 16));
    const unsigned bLane = (unsigned)(((l & 7) + ((l & 16) >> 1))*PITCH + ((l & 8) << 1));
    const unsigned aBase = (unsigned)((wm << 6)*PITCH) + aLane;
    const unsigned bBase = (unsigned)((wn << 6)*PITCH) + bLane;

    // B producer mapping: 8 threads per 128B row chunk, rows pr + 32j
    const int pr  = t >> 3;
    const int pc  = (t & 7) << 4;
    const char* bG = (const char*)g_w2b + ((size_t)pr << 10) + pc;
    const unsigned sBp = sb + SB_OFF + pr*PITCH + pc;

    // A producer mapping: rows (t>>4) + 16i, float4 index t&15
    const int arb = t >> 4;
    const int af4 = t & 15;
    const float* hdB = g_hd + ((size_t)b << 16);

    // he + b1 -> sHE
    if (t < 128){
        float4 h  = ((const float4*)(g_he + (size_t)bm*Ddim))[t];
        float4 bb = ((const float4*)b1)[t];
        float4 v; v.x = h.x+bb.x; v.y = h.y+bb.y; v.z = h.z+bb.z; v.w = h.w+bb.w;
        ((float4*)sHE)[t] = v;
    }
    // B chunk 0 (pass 0) -> stage 0
#pragma unroll
    for (int j = 0; j < 8; j++)
        cpa16(sBp + (j << 5)*PITCH, bG + ((size_t)(j << 5) << 10));
    CPA_COMMIT();
    __syncthreads();      // sHE visible for A production

    float m8[8], s8[8];
#pragma unroll
    for (int i = 0; i < 8; i++){ m8[i] = -3.4e38f; s8[i] = 0.f; }
    float acc[4][8][4];

#pragma unroll 1
    for (int q = 0; q < 32; q++){
        const int pass = q >> 3, kc = q & 7, buf = q & 1;

        // pass 0: produce A chunk q = bf16(tanh(he + b1 + hd)) into resident sA
        if (q < 8){
            char* dA = smemc + q*ACHUNK;
            const float* hesrc = sHE + (q << 6) + (af4 << 2);
            float4 h = *(const float4*)hesrc;
#pragma unroll
            for (int i = 0; i < 8; i++){
                const int row = arb + (i << 4);
                float4 d = *(const float4*)(hdB + (size_t)row*Ddim + (q << 6) + (af4 << 2));
                uint2 o;
                o.x = pk(tanh_fast(h.x + d.x), tanh_fast(h.y + d.y));
                o.y = pk(tanh_fast(h.z + d.z), tanh_fast(h.w + d.w));
                *(uint2*)(dA + row*PITCH + (af4 << 3)) = o;
            }
        }

        CPA_WAIT0();          // B stage q&1 complete
        __syncthreads();      // all copies + A production visible

        // issue B copy for q+1 into the other stage (overlaps mma + epilogue)
        if (q < 31){
            const int qn = q + 1, pn = qn >> 3, kn = qn & 7;
            const char* bsrc = bG + ((size_t)(pn << 8) << 10) + (kn << 7);
            const unsigned bdst = sBp + (qn & 1)*B_BUF;
#pragma unroll
            for (int j = 0; j < 8; j++)
                cpa16(bdst + (j << 5)*PITCH, bsrc + ((size_t)(j << 5) << 10));
            CPA_COMMIT();
        }

        if (kc == 0){
#pragma unroll
            for (int mt = 0; mt < 4; mt++)
#pragma unroll
                for (int nt = 0; nt < 8; nt++)
#pragma unroll
                    for (int i = 0; i < 4; i++) acc[mt][nt][i] = 0.f;
        }

        // mma over chunk kc (4 k16 steps), ldmatrix fragment loads
        const unsigned aCh = sb + kc*ACHUNK + aBase;
        const unsigned bCh = sb + SB_OFF + buf*B_BUF + bBase;
#pragma unroll
        for (int s = 0; s < 4; s++){
            const unsigned off = s << 5;
            unsigned af[4][4], bq[4][4];
#pragma unroll
            for (int mt = 0; mt < 4; mt++)
                ldsm4(af[mt], aCh + (mt << 4)*PITCH + off);
#pragma unroll
            for (int np = 0; np < 4; np++)
                ldsm4(bq[np], bCh + (np << 4)*PITCH + off);
#pragma unroll
            for (int mt = 0; mt < 4; mt++)
#pragma unroll
                for (int nt = 0; nt < 8; nt++)
                    mma_bf16(acc[mt][nt], af[mt], &bq[nt >> 1][(nt & 1) << 1]);
        }

        // pass epilogue: +b2, write logits, merge online (max, sumexp)
        if (kc == 7){
            const int colb = (pass << 8) + (wn << 6);
#pragma unroll
            for (int mt = 0; mt < 4; mt++){
#pragma unroll
                for (int h = 0; h < 2; h++){
                    const int r = (wm << 6) + (mt << 4) + lq + (h << 3);
                    const int g = g0 + r;
                    float v[16];
                    float gm = -3.4e38f;
#pragma unroll
                    for (int nt = 0; nt < 8; nt++){
                        const int c = colb + (nt << 3) + (lr << 1);
                        float x0 = acc[mt][nt][h*2 + 0] + __ldg(b2 + c);
                        float x1 = acc[mt][nt][h*2 + 1] + __ldg(b2 + c + 1);
                        v[2*nt] = x0; v[2*nt + 1] = x1;
                        gm = fmaxf(gm, fmaxf(x0, x1));
                        float2 st; st.x = x0; st.y = x1;
                        *(float2*)(out + (size_t)g*Cdim + c) = st;
                    }
                    float gs = 0.f;
#pragma unroll
                    for (int i = 0; i < 16; i++) gs += __expf(v[i] - gm);
                    const int slot = (mt << 1) + h;
                    float mn = fmaxf(m8[slot], gm);
                    s8[slot] = s8[slot]*__expf(m8[slot] - mn) + gs*__expf(gm - mn);
                    m8[slot] = mn;
                }
            }
        }
    }

    // ---- cross-lane (lr) reduction of (m, s) ----
#pragma unroll
    for (int i = 0; i < 8; i++){
#pragma unroll
        for (int k = 1; k <= 2; k <<= 1){
            float om = __shfl_xor_sync(0xffffffffu, m8[i], k);
            float os = __shfl_xor_sync(0xffffffffu, s8[i], k);
            float mn = fmaxf(m8[i], om);
            s8[i] = s8[i]*__expf(m8[i] - mn) + os*__expf(om - mn);
            m8[i] = mn;
        }
    }
    __syncthreads();   // B stages dead; reuse as reduction area
    float* sred = (float*)(smemc + SB_OFF);          // [128][4] float2
    float* slse = (float*)(smemc + SB_OFF + 4096);   // [128]
    if (lr == 0){
#pragma unroll
        for (int i = 0; i < 8; i++){
            const int r = (wm << 6) + ((i >> 1) << 4) + lq + ((i & 1) << 3);
            float2 p; p.x = m8[i]; p.y = s8[i];
            *(float2*)(sred + ((r << 2) + wn)*2) = p;
        }
    }
    __syncthreads();
    if (t < 128){
        const float2* p = (const float2*)(sred + (t << 3));
        float2 q0 = p[0], q1 = p[1], q2 = p[2], q3 = p[3];
        float mx = fmaxf(fmaxf(q0.x, q1.x), fmaxf(q2.x, q3.x));
        float s  = q0.y*__expf(q0.x - mx) + q1.y*__expf(q1.x - mx)
                 + q2.y*__expf(q2.x - mx) + q3.y*__expf(q3.x - mx);
        slse[t] = mx + __logf(s);
    }
    __syncthreads();

    // ---- final: out -= lse (tile is L2-hot) ----
    float4* outB = (float4*)out + ((size_t)g0 << 8);   // 256 float4 per row
#pragma unroll 4
    for (int i = t; i < 128*256; i += 256){
        const float lse = slse[i >> 8];
        float4 v = outB[i];
        v.x -= lse; v.y -= lse; v.z -= lse; v.w -= lse;
        __stcs(outB + i, v);
    }
}

// ================= launch =================
extern "C" void kernel_launch(void* const* d_in, const int* in_sizes, int n_in,
                              void* d_out, int out_size){
    (void)in_sizes; (void)n_in; (void)out_size;
    const float* enc = (const float*)d_in[0];
    const float* dec = (const float*)d_in[1];
    const float* w1  = (const float*)d_in[2];
    const float* b1  = (const float*)d_in[3];
    const float* w2  = (const float*)d_in[4];
    const float* b2  = (const float*)d_in[5];
    float* out = (float*)d_out;

    cudaFuncSetAttribute(fused_k, cudaFuncAttributeMaxDynamicSharedMemorySize, SMEM_TOT);

    cvtw2b_k<<<(Cdim*Ddim/8)/256, 256>>>(w2);
    fc1_k<<<dim3(8, 24), 256>>>(enc, dec, w1);
    fused_k<<<1024, 256, SMEM_TOT>>>(b1, b2, out);
}

// round 13
// speedup vs baseline: 1.8502x; 1.0573x over previous
#include <cuda_runtime.h>
#include <cuda_bf16.h>
#include <cstdint>

// Problem dims
#define Bdim 4
#define Mdim 256
#define Ndim 128
#define Ddim 512
#define Cdim 1024
#define ROWS (Bdim*Mdim*Ndim)   // 131072

// -------- scratch (device globals) --------
__device__ float g_he[Bdim*Mdim*Ddim];          // 2 MB
__device__ float g_hd[Bdim*Ndim*Ddim];          // 1 MB
__device__ __nv_bfloat16 g_w2b[Cdim*Ddim];      // 1 MB   w2 -> bf16

// -------- helpers --------
__device__ __forceinline__ float tanh_fast(float x){
    float r; asm("tanh.approx.f32 %0, %1;" : "=f"(r) : "f"(x)); return r;
}
__device__ __forceinline__ unsigned pk(float lo, float hi){
    unsigned r;
    asm("cvt.rn.bf16x2.f32 %0, %2, %1;" : "=r"(r) : "f"(lo), "f"(hi));
    return r;
}
__device__ __forceinline__ void mma_bf16(float* d, const unsigned* a, const unsigned* b){
    asm volatile(
        "mma.sync.aligned.m16n8k16.row.col.f32.bf16.bf16.f32 "
        "{%0,%1,%2,%3}, {%4,%5,%6,%7}, {%8,%9}, {%0,%1,%2,%3};\n"
        : "+f"(d[0]), "+f"(d[1]), "+f"(d[2]), "+f"(d[3])
        : "r"(a[0]), "r"(a[1]), "r"(a[2]), "r"(a[3]), "r"(b[0]), "r"(b[1]));
}
__device__ __forceinline__ void ldsm4(unsigned* r, unsigned addr){
    asm volatile("ldmatrix.sync.aligned.m8n8.x4.shared.b16 {%0,%1,%2,%3}, [%4];"
        : "=r"(r[0]), "=r"(r[1]), "=r"(r[2]), "=r"(r[3]) : "r"(addr));
}
__device__ __forceinline__ unsigned smem_u32(const void* p){
    unsigned a;
    asm("{ .reg .u64 t; cvta.to.shared.u64 t, %1; cvt.u32.u64 %0, t; }" : "=r"(a) : "l"(p));
    return a;
}
__device__ __forceinline__ void cpa16(unsigned saddr, const void* g){
    asm volatile("cp.async.cg.shared.global [%0], [%1], 16;" :: "r"(saddr), "l"(g));
}
#define CPA_COMMIT() asm volatile("cp.async.commit_group;" ::: "memory")
#define CPA_WAIT0()  asm volatile("cp.async.wait_group 0;" ::: "memory")

// ================= K0: w2 -> bf16 =================
__global__ __launch_bounds__(256) void cvtw2b_k(const float* __restrict__ w2){
    const int i = blockIdx.x*256 + threadIdx.x;
    float4 v0 = ((const float4*)w2)[2*i];
    float4 v1 = ((const float4*)w2)[2*i + 1];
    uint4 o;
    o.x = pk(v0.x, v0.y); o.y = pk(v0.z, v0.w);
    o.z = pk(v1.x, v1.y); o.w = pk(v1.z, v1.w);
    ((uint4*)g_w2b)[i] = o;
}

// ================= K1: fc1 both GEMMs in one launch (fp32, exact) ==============
__global__ __launch_bounds__(256) void fc1_k(const float* __restrict__ enc,
                                             const float* __restrict__ dec,
                                             const float* __restrict__ W){
    __shared__ float sX[16][64];
    __shared__ float sW[16][64];
    const int by = blockIdx.y;
    const int which = (by >= 16);
    const float* __restrict__ X = which ? dec : enc;
    float* __restrict__ Y = which ? g_hd : g_he;
    const int woff = which ? Ddim : 0;
    const int rb = (which ? (by - 16) : by) << 6;
    const int t  = threadIdx.x;
    const int tx = t & 15, ty = t >> 4;
    const int eb = blockIdx.x << 6;
    const int r  = t >> 2, kq = (t & 3) << 2;

    float acc[4][4];
#pragma unroll
    for (int i = 0; i < 4; i++)
#pragma unroll
        for (int j = 0; j < 4; j++) acc[i][j] = 0.f;

    for (int k0 = 0; k0 < Ddim; k0 += 16){
        float4 xv = *(const float4*)(X + (rb + r)*Ddim + k0 + kq);
        float4 wv = *(const float4*)(W + (eb + r)*(2*Ddim) + woff + k0 + kq);
        __syncthreads();
        sX[kq+0][r] = xv.x; sX[kq+1][r] = xv.y; sX[kq+2][r] = xv.z; sX[kq+3][r] = xv.w;
        sW[kq+0][r] = wv.x; sW[kq+1][r] = wv.y; sW[kq+2][r] = wv.z; sW[kq+3][r] = wv.w;
        __syncthreads();
#pragma unroll
        for (int k = 0; k < 16; k++){
            float4 a  = *(const float4*)&sX[k][ty << 2];
            float4 bv = *(const float4*)&sW[k][tx << 2];
            float av[4] = {a.x, a.y, a.z, a.w};
            float bb[4] = {bv.x, bv.y, bv.z, bv.w};
#pragma unroll
            for (int i = 0; i < 4; i++)
#pragma unroll
                for (int j = 0; j < 4; j++) acc[i][j] = fmaf(av[i], bb[j], acc[i][j]);
        }
    }
#pragma unroll
    for (int i = 0; i < 4; i++)
#pragma unroll
        for (int j = 0; j < 4; j++)
            Y[(rb + (ty<<2) + i)*Ddim + eb + (tx<<2) + j] = acc[i][j];
}

// ================= K2: fused tanh + GEMM + log-softmax =========================
// One CTA per bm (grid 1024), 512 threads, 16 warps as 2(m) x 8(n),
// warp tile 64x32. 128 rows x ALL 1024 cols in 4 col-passes of 256.
// K=512 in 8 chunks of 64. A produced in-kernel and resident in smem.
// smem: sA 8x18432 = 147456, sB 2x36864 = 73728, sHE 2048  (= 223232)
#define PITCH   144
#define ACHUNK  18432
#define SB_OFF  147456
#define B_BUF   36864
#define SHE_OFF 221184
#define SMEM_TOT 223232

__global__ __launch_bounds__(512,1) void fused_k(const float* __restrict__ b1,
                                                 const float* __restrict__ b2,
                                                 float* __restrict__ out){
    extern __shared__ __align__(128) char smemc[];
    const unsigned sb = smem_u32(smemc);

    const int bm  = blockIdx.x;     // 0..1023
    const int g0  = bm << 7;        // first global row
    const int b   = bm >> 8;        // batch
    const int t   = threadIdx.x;
    const int w   = t >> 5, l = t & 31;
    const int wm  = w >> 3, wn = w & 7;      // 2(m) x 8(n)
    const int lq  = l >> 2, lr = l & 3;

    float* sHE = (float*)(smemc + SHE_OFF);

    // ldmatrix per-lane base offsets
    const unsigned aLane = (unsigned)((l & 15)*PITCH + (l & 16));
    const unsigned bLane = (unsigned)(((l & 7) + ((l & 16) >> 1))*PITCH + ((l & 8) << 1));
    const unsigned aBase = (unsigned)((wm << 6)*PITCH) + aLane;
    const unsigned bBase = (unsigned)((wn << 5)*PITCH) + bLane;

    // B producer mapping: 8 threads per 128B row chunk; rows (t>>3) + 64j, j<4
    const int pr  = t >> 3;          // 0..63
    const int pc  = (t & 7) << 4;
    const char* bG = (const char*)g_w2b + ((size_t)pr << 10) + pc;
    const unsigned sBp = sb + SB_OFF + pr*PITCH + pc;

    // A producer mapping: rows (t>>4) + 32i (i<4), float4 slot t&15
    const int arb = t >> 4;          // 0..31
    const int af4 = t & 15;
    const float* hdB = g_hd + ((size_t)b << 16);

    // he + b1 -> sHE
    if (t < 128){
        float4 h  = ((const float4*)(g_he + (size_t)bm*Ddim))[t];
        float4 bb = ((const float4*)b1)[t];
        float4 v; v.x = h.x+bb.x; v.y = h.y+bb.y; v.z = h.z+bb.z; v.w = h.w+bb.w;
        ((float4*)sHE)[t] = v;
    }
    // B chunk 0 (pass 0) -> stage 0
#pragma unroll
    for (int j = 0; j < 4; j++)
        cpa16(sBp + (j << 6)*PITCH, bG + ((size_t)(j << 6) << 10));
    CPA_COMMIT();
    __syncthreads();      // sHE visible for A production

    float m8[8], s8[8];
#pragma unroll
    for (int i = 0; i < 8; i++){ m8[i] = -3.4e38f; s8[i] = 0.f; }
    float acc[4][4][4];   // [mt][nt][frag] — 64 regs

#pragma unroll 1
    for (int q = 0; q < 32; q++){
        const int pass = q >> 3, kc = q & 7, buf = q & 1;

        // pass 0: produce A chunk q = bf16(tanh(he + b1 + hd)) into resident sA
        if (q < 8){
            char* dA = smemc + q*ACHUNK;
            float4 h = *(const float4*)(sHE + (q << 6) + (af4 << 2));
#pragma unroll
            for (int i = 0; i < 4; i++){
                const int row = arb + (i << 5);
                float4 d = *(const float4*)(hdB + (size_t)row*Ddim + (q << 6) + (af4 << 2));
                uint2 o;
                o.x = pk(tanh_fast(h.x + d.x), tanh_fast(h.y + d.y));
                o.y = pk(tanh_fast(h.z + d.z), tanh_fast(h.w + d.w));
                *(uint2*)(dA + row*PITCH + (af4 << 3)) = o;
            }
        }

        CPA_WAIT0();          // B stage q&1 complete
        __syncthreads();      // all copies + A production visible

        // issue B copy for q+1 into the other stage
        if (q < 31){
            const int qn = q + 1, pn = qn >> 3, kn = qn & 7;
            const char* bsrc = bG + ((size_t)(pn << 8) << 10) + (kn << 7);
            const unsigned bdst = sBp + (qn & 1)*B_BUF;
#pragma unroll
            for (int j = 0; j < 4; j++)
                cpa16(bdst + (j << 6)*PITCH, bsrc + ((size_t)(j << 6) << 10));
            CPA_COMMIT();
        }

        if (kc == 0){
#pragma unroll
            for (int mt = 0; mt < 4; mt++)
#pragma unroll
                for (int nt = 0; nt < 4; nt++)
#pragma unroll
                    for (int i = 0; i < 4; i++) acc[mt][nt][i] = 0.f;
        }

        // mma over chunk kc (4 k16 steps), ldmatrix fragment loads
        const unsigned aCh = sb + kc*ACHUNK + aBase;
        const unsigned bCh = sb + SB_OFF + buf*B_BUF + bBase;
#pragma unroll
        for (int s = 0; s < 4; s++){
            const unsigned off = s << 5;
            unsigned af[4][4], bq[2][4];
#pragma unroll
            for (int mt = 0; mt < 4; mt++)
                ldsm4(af[mt], aCh + (mt << 4)*PITCH + off);
#pragma unroll
            for (int np = 0; np < 2; np++)
                ldsm4(bq[np], bCh + (np << 4)*PITCH + off);
#pragma unroll
            for (int mt = 0; mt < 4; mt++)
#pragma unroll
                for (int nt = 0; nt < 4; nt++)
                    mma_bf16(acc[mt][nt], af[mt], &bq[nt >> 1][(nt & 1) << 1]);
        }

        // pass epilogue: +b2, write logits, merge online (max, sumexp)
        if (kc == 7){
            const int colb = (pass << 8) + (wn << 5);
#pragma unroll
            for (int mt = 0; mt < 4; mt++){
#pragma unroll
                for (int h = 0; h < 2; h++){
                    const int r = (wm << 6) + (mt << 4) + lq + (h << 3);
                    const int g = g0 + r;
                    float v[8];
                    float gm = -3.4e38f;
#pragma unroll
                    for (int nt = 0; nt < 4; nt++){
                        const int c = colb + (nt << 3) + (lr << 1);
                        float x0 = acc[mt][nt][h*2 + 0] + __ldg(b2 + c);
                        float x1 = acc[mt][nt][h*2 + 1] + __ldg(b2 + c + 1);
                        v[2*nt] = x0; v[2*nt + 1] = x1;
                        gm = fmaxf(gm, fmaxf(x0, x1));
                        float2 st; st.x = x0; st.y = x1;
                        *(float2*)(out + (size_t)g*Cdim + c) = st;
                    }
                    float gs = 0.f;
#pragma unroll
                    for (int i = 0; i < 8; i++) gs += __expf(v[i] - gm);
                    const int slot = (mt << 1) + h;
                    float mn = fmaxf(m8[slot], gm);
                    s8[slot] = s8[slot]*__expf(m8[slot] - mn) + gs*__expf(gm - mn);
                    m8[slot] = mn;
                }
            }
        }
    }

    // ---- cross-lane (lr) reduction of (m, s) ----
#pragma unroll
    for (int i = 0; i < 8; i++){
#pragma unroll
        for (int k = 1; k <= 2; k <<= 1){
            float om = __shfl_xor_sync(0xffffffffu, m8[i], k);
            float os = __shfl_xor_sync(0xffffffffu, s8[i], k);
            float mn = fmaxf(m8[i], om);
            s8[i] = s8[i]*__expf(m8[i] - mn) + os*__expf(om - mn);
            m8[i] = mn;
        }
    }
    __syncthreads();   // B stages dead; reuse as reduction area
    float* sred = (float*)(smemc + SB_OFF);          // [128][8] float2
    float* slse = (float*)(smemc + SB_OFF + 8192);   // [128]
    if (lr == 0){
#pragma unroll
        for (int i = 0; i < 8; i++){
            const int r = (wm << 6) + ((i >> 1) << 4) + lq + ((i & 1) << 3);
            float2 p; p.x = m8[i]; p.y = s8[i];
            *(float2*)(sred + ((r << 3) + wn)*2) = p;
        }
    }
    __syncthreads();
    if (t < 128){
        const float2* p = (const float2*)(sred + (t << 4));
        float mx = -3.4e38f;
#pragma unroll
        for (int i = 0; i < 8; i++) mx = fmaxf(mx, p[i].x);
        float s = 0.f;
#pragma unroll
        for (int i = 0; i < 8; i++) s += p[i].y*__expf(p[i].x - mx);
        slse[t] = mx + __logf(s);
    }
    __syncthreads();

    // ---- final: out -= lse (tile is L2-hot) ----
    float4* outB = (float4*)out + ((size_t)g0 << 8);   // 256 float4 per row
#pragma unroll 4
    for (int i = t; i < 128*256; i += 512){
        const float lse = slse[i >> 8];
        float4 v = outB[i];
        v.x -= lse; v.y -= lse; v.z -= lse; v.w -= lse;
        __stcs(outB + i, v);
    }
}

// ================= launch =================
extern "C" void kernel_launch(void* const* d_in, const int* in_sizes, int n_in,
                              void* d_out, int out_size){
    (void)in_sizes; (void)n_in; (void)out_size;
    const float* enc = (const float*)d_in[0];
    const float* dec = (const float*)d_in[1];
    const float* w1  = (const float*)d_in[2];
    const float* b1  = (const float*)d_in[3];
    const float* w2  = (const float*)d_in[4];
    const float* b2  = (const float*)d_in[5];
    float* out = (float*)d_out;

    cudaFuncSetAttribute(fused_k, cudaFuncAttributeMaxDynamicSharedMemorySize, SMEM_TOT);

    cvtw2b_k<<<(Cdim*Ddim/8)/256, 256>>>(w2);
    fc1_k<<<dim3(8, 24), 256>>>(enc, dec, w1);
    fused_k<<<1024, 512, SMEM_TOT>>>(b1, b2, out);
}